// round 12
// baseline (speedup 1.0000x reference)
#include <cuda_runtime.h>
#include <cuda_bf16.h>
#include <math.h>
#include <float.h>
#include <stdint.h>

#define BN 8
#define TN 4096
#define DN 256
#define INNER 512
#define SN 16
#define BT 32768
#define NCODE 240
#define CHUNK 256
#define WARM 32
#define NCHUNK (TN / CHUNK)

// ---------------- scratch ----------------
__device__ float g_gT[(size_t)INNER * BT];
__device__ float g_xc[(size_t)BT * INNER];
__device__ float g_xcT[(size_t)INNER * BT];
__device__ float g_dtT[(size_t)INNER * BT];
__device__ float g_bcT[(size_t)32 * BT];
__device__ uint32_t g_xsh[(size_t)BT * 128], g_xsl[(size_t)BT * 128];
__device__ uint32_t g_xmh[(size_t)BT * 256], g_xml[(size_t)BT * 256];
__device__ uint32_t g_xch[(size_t)BT * 256], g_xcl[(size_t)BT * 256];
__device__ uint32_t g_ygh[(size_t)256 * BT], g_ygl[(size_t)256 * BT];   // [kp][bt]
__device__ uint32_t g_w1h[131072], g_w1l[131072];  // [n=1024][kp=128]
__device__ uint32_t g_w2h[131072], g_w2l[131072];  // [n=512][kp=256]
__device__ uint32_t g_w3h[131072], g_w3l[131072];  // [n=512][kp=256]
__device__ uint32_t g_w4h[65536],  g_w4l[65536];   // out_w^T [m=256][kp=256]

// ---------------- math ----------------
__device__ __forceinline__ float fexp(float x) {
    float t = x * 1.4426950408889634f;
    t = fminf(fmaxf(t, -100.f), 100.f);
    float z = t + 12582912.0f;
    int n = __float_as_int(z) - 0x4B400000;
    float r = t - (z - 12582912.0f);
    float p = 1.5403530394e-4f;
    p = fmaf(p, r, 1.3333558146e-3f);
    p = fmaf(p, r, 9.6181291076e-3f);
    p = fmaf(p, r, 5.5504108664e-2f);
    p = fmaf(p, r, 2.4022650696e-1f);
    p = fmaf(p, r, 6.9314718056e-1f);
    p = fmaf(p, r, 1.0f);
    return __int_as_float(__float_as_int(p) + (n << 23));
}
__device__ __forceinline__ float frcp_fast(float x) {
    float r = __uint_as_float(0x7EF311C3u - __float_as_uint(x));
    r = r * (2.f - x * r); r = r * (2.f - x * r); r = r * (2.f - x * r);
    return r;
}
__device__ __forceinline__ float fsig(float x)  { return frcp_fast(1.f + fexp(-x)); }
__device__ __forceinline__ float fsilu(float x) { return x * fsig(x); }
__device__ __forceinline__ float sigf(float x)  { return 1.f / (1.f + __expf(-x)); }
__device__ __forceinline__ float softplusf(float x) {
    return x > 20.f ? x : __logf(1.f + fexp(x));
}
__device__ __forceinline__ float geluf(float x) {
    const float c = 0.7978845608028654f;
    float t = tanhf(c * (x + 0.044715f * x * x * x));
    return 0.5f * x * (1.f + t);
}
__device__ __forceinline__ void bsplit2(float f0, float f1, uint32_t& hi, uint32_t& lo) {
    __nv_bfloat16 h0 = __float2bfloat16_rn(f0);
    __nv_bfloat16 h1 = __float2bfloat16_rn(f1);
    __nv_bfloat162 hh; hh.x = h0; hh.y = h1;
    hi = *reinterpret_cast<uint32_t*>(&hh);
    __nv_bfloat162 ll = __floats2bfloat162_rn(f0 - __bfloat162float(h0),
                                              f1 - __bfloat162float(h1));
    lo = *reinterpret_cast<uint32_t*>(&ll);
}
__device__ __forceinline__ void mma_bf16(float c[4], const uint32_t a[4], const uint32_t b[2]) {
    asm volatile(
        "mma.sync.aligned.m16n8k16.row.col.f32.bf16.bf16.f32 "
        "{%0,%1,%2,%3}, {%4,%5,%6,%7}, {%8,%9}, {%0,%1,%2,%3};\n"
        : "+f"(c[0]), "+f"(c[1]), "+f"(c[2]), "+f"(c[3])
        : "r"(a[0]), "r"(a[1]), "r"(a[2]), "r"(a[3]), "r"(b[0]), "r"(b[1]));
}
__device__ __forceinline__ void ldsm4(uint32_t& r0, uint32_t& r1, uint32_t& r2,
                                      uint32_t& r3, uint32_t addr) {
    asm volatile("ldmatrix.sync.aligned.m8n8.x4.shared.b16 {%0,%1,%2,%3}, [%4];"
                 : "=r"(r0), "=r"(r1), "=r"(r2), "=r"(r3) : "r"(addr));
}
__device__ __forceinline__ void cp16(uint32_t s, const void* g) {
    asm volatile("cp.async.cg.shared.global [%0], [%1], 16;\n" :: "r"(s), "l"(g));
}
__device__ __forceinline__ void cp_commit() { asm volatile("cp.async.commit_group;\n"); }
__device__ __forceinline__ void cp_wait1()  { asm volatile("cp.async.wait_group 1;\n"); }

// ---------------- prep kernels ----------------
__global__ __launch_bounds__(256)
void wprepB(const float* __restrict__ W, uint32_t* __restrict__ Wh,
            uint32_t* __restrict__ Wl, int N, int KP) {
    int i = blockIdx.x * 256 + threadIdx.x;
    if (i >= N * KP) return;
    int n = i / KP, kp = i - n * KP;
    bsplit2(W[(size_t)(2 * kp) * N + n], W[(size_t)(2 * kp + 1) * N + n], Wh[i], Wl[i]);
}
__global__ __launch_bounds__(256)
void wprepT(const float* __restrict__ W, uint32_t* __restrict__ Wh,
            uint32_t* __restrict__ Wl, int Mn, int KP) {
    int i = blockIdx.x * 256 + threadIdx.x;
    if (i >= Mn * KP) return;
    int m = i / KP, kp = i - m * KP;
    bsplit2(W[(size_t)(2 * kp) * Mn + m], W[(size_t)(2 * kp + 1) * Mn + m], Wh[i], Wl[i]);
}
__global__ __launch_bounds__(256)
void xsplit(const float* __restrict__ x, uint32_t* __restrict__ xh,
            uint32_t* __restrict__ xl) {
    size_t i = (size_t)blockIdx.x * 256 + threadIdx.x;
    float2 v = *(const float2*)(x + 2 * i);
    bsplit2(v.x, v.y, xh[i], xl[i]);
}

// ---------------- bf16x3 GEMM, cp.async ring + ldmatrix --------------------
// A split [row][kp] (ldaP), ldmatrix. B: if !BKM split [n][kp] (ldbP), ldmatrix;
// if BKM split [kp][n] (ldbP = n-row length), scalar-LDS fragments (out_proj).
// The 3 bf16x3 terms are issued as 3 passes over all 16 (mf,nf) tiles so
// accumulator-dependent MMAs are 16 instructions apart (no RAW stalls).
// Per-acc accumulation order unchanged: Al*Bh, Ah*Bl, Ah*Bh.
#define PITCH 12
#define BPITCH 136
#define TSTG  (128 * PITCH)
#define SMEMB (12 * TSTG * 4)

template <int EPI, int MODE, bool BROW, bool EMIT, bool BKM>
__global__ __launch_bounds__(256)
void tgemm(const uint32_t* __restrict__ Ah, const uint32_t* __restrict__ Al, int ldaP,
           const uint32_t* __restrict__ Bh, const uint32_t* __restrict__ Bl, int ldbP,
           const float* __restrict__ bias,
           float* __restrict__ C, int ldc, float* __restrict__ Ct,
           uint32_t* __restrict__ Oh, uint32_t* __restrict__ Ol, int ldoP, int K)
{
    extern __shared__ uint32_t smq[];
    const int tid = threadIdx.x, lane = tid & 31, warp = tid >> 5;
    const int wm = warp >> 2, wn = warp & 3;
    const int bm = blockIdx.y * 128, bn = blockIdx.x * 128;
    const int M = gridDim.y * 128;

    const int ar = tid >> 1, ap = (tid & 1) << 2;
    const uint32_t smem0 = (uint32_t)__cvta_generic_to_shared(smq);
    const uint32_t awrd = smem0 + (uint32_t)(ar * PITCH + ap) * 4;
    const uint32_t bwrd_km = smem0 + (uint32_t)(warp * BPITCH + (lane << 2)) * 4;

    const uint32_t* Agh = Ah + (size_t)(bm + ar) * ldaP + ap;
    const uint32_t* Agl = Al + (size_t)(bm + ar) * ldaP + ap;
    const uint32_t* Bgh;
    const uint32_t* Bgl;
    if (BKM) {
        Bgh = Bh + (size_t)warp * ldbP + bn + (lane << 2);
        Bgl = Bl + (size_t)warp * ldbP + bn + (lane << 2);
    } else {
        Bgh = Bh + (size_t)(bn + ar) * ldbP + ap;
        Bgl = Bl + (size_t)(bn + ar) * ldbP + ap;
    }

    const uint32_t aoff = (uint32_t)(((wm * 64 + ((lane >> 3) & 1) * 8 + (lane & 7)) * PITCH
                                      + (lane >> 4) * 4) * 4);
    const uint32_t boff = (uint32_t)(((wn * 32 + ((lane >> 4) & 1) * 8 + (lane & 7)) * PITCH
                                      + ((lane >> 3) & 1) * 4) * 4);

    const int NT = K >> 4;
    float acc[4][4][4];
#pragma unroll
    for (int i = 0; i < 4; i++)
#pragma unroll
        for (int j = 0; j < 4; j++)
#pragma unroll
            for (int r = 0; r < 4; r++) acc[i][j][r] = 0.f;

    auto load_tile = [&](int t, int st) {
        const int kp0 = t * 8;
        cp16(awrd + (uint32_t)((st * 4 + 0) * TSTG) * 4, Agh + kp0);
        cp16(awrd + (uint32_t)((st * 4 + 1) * TSTG) * 4, Agl + kp0);
        if (BKM) {
            cp16(bwrd_km + (uint32_t)((st * 4 + 2) * TSTG) * 4, Bgh + (size_t)kp0 * ldbP);
            cp16(bwrd_km + (uint32_t)((st * 4 + 3) * TSTG) * 4, Bgl + (size_t)kp0 * ldbP);
        } else {
            cp16(awrd + (uint32_t)((st * 4 + 2) * TSTG) * 4, Bgh + kp0);
            cp16(awrd + (uint32_t)((st * 4 + 3) * TSTG) * 4, Bgl + kp0);
        }
    };
    load_tile(0, 0); cp_commit();
    load_tile(1, 1); cp_commit();

    const int tig = lane & 3, gid = lane >> 2;
    int st = 0;
    for (int i = 0; i < NT; i++) {
        cp_wait1();
        __syncthreads();
        int stn = st + 2; if (stn >= 3) stn -= 3;
        if (i + 2 < NT) load_tile(i + 2, stn);
        cp_commit();

        const uint32_t bAh = smem0 + (uint32_t)((st * 4 + 0) * TSTG) * 4;
        const uint32_t bAl = smem0 + (uint32_t)((st * 4 + 1) * TSTG) * 4;

        uint32_t afh[4][4], afl[4][4], bfh[4][2], bfl[4][2];
#pragma unroll
        for (int mf = 0; mf < 4; mf++) {
            ldsm4(afh[mf][0], afh[mf][1], afh[mf][2], afh[mf][3], bAh + aoff + mf * (16 * PITCH * 4));
            ldsm4(afl[mf][0], afl[mf][1], afl[mf][2], afl[mf][3], bAl + aoff + mf * (16 * PITCH * 4));
        }
        if (BKM) {
            const uint32_t* Bsh = smq + (st * 4 + 2) * TSTG;
            const uint32_t* Bsl = smq + (st * 4 + 3) * TSTG;
#pragma unroll
            for (int nf = 0; nf < 4; nf++) {
                const int nn = wn * 32 + nf * 8 + gid;
                bfh[nf][0] = Bsh[tig * BPITCH + nn];
                bfh[nf][1] = Bsh[(tig + 4) * BPITCH + nn];
                bfl[nf][0] = Bsl[tig * BPITCH + nn];
                bfl[nf][1] = Bsl[(tig + 4) * BPITCH + nn];
            }
        } else {
            const uint32_t bBh = smem0 + (uint32_t)((st * 4 + 2) * TSTG) * 4;
            const uint32_t bBl = smem0 + (uint32_t)((st * 4 + 3) * TSTG) * 4;
#pragma unroll
            for (int p = 0; p < 2; p++) {
                ldsm4(bfh[2 * p][0], bfh[2 * p][1], bfh[2 * p + 1][0], bfh[2 * p + 1][1],
                      bBh + boff + p * (16 * PITCH * 4));
                ldsm4(bfl[2 * p][0], bfl[2 * p][1], bfl[2 * p + 1][0], bfl[2 * p + 1][1],
                      bBl + boff + p * (16 * PITCH * 4));
            }
        }
        // ---- 3 passes: dependent MMAs on the same acc are 16 apart ----
#pragma unroll
        for (int mf = 0; mf < 4; mf++)
#pragma unroll
            for (int nf = 0; nf < 4; nf++)
                mma_bf16(acc[mf][nf], afl[mf], bfh[nf]);
#pragma unroll
        for (int mf = 0; mf < 4; mf++)
#pragma unroll
            for (int nf = 0; nf < 4; nf++)
                mma_bf16(acc[mf][nf], afh[mf], bfl[nf]);
#pragma unroll
        for (int mf = 0; mf < 4; mf++)
#pragma unroll
            for (int nf = 0; nf < 4; nf++)
                mma_bf16(acc[mf][nf], afh[mf], bfh[nf]);

        st = (st + 1 == 3) ? 0 : st + 1;
    }

    // epilogue
#pragma unroll
    for (int mf = 0; mf < 4; mf++) {
#pragma unroll
        for (int nf = 0; nf < 4; nf++) {
            const int col = wn * 32 + nf * 8 + tig * 2;
            const int row = wm * 64 + mf * 16 + gid;
            float b0, b1, b2, b3;
            if (BROW) { b0 = b1 = bias[bm + row]; b2 = b3 = bias[bm + row + 8]; }
            else      { b0 = b2 = bias[bn + col]; b1 = b3 = bias[bn + col + 1]; }
            float v0 = acc[mf][nf][0] + b0;
            float v1 = acc[mf][nf][1] + b1;
            float v2 = acc[mf][nf][2] + b2;
            float v3 = acc[mf][nf][3] + b3;
            if (MODE != 3) {
                if (EPI == 1) { v0 = fsilu(v0); v1 = fsilu(v1); v2 = fsilu(v2); v3 = fsilu(v3); }
                else if (EPI == 2) { v0 = softplusf(v0); v1 = softplusf(v1); v2 = softplusf(v2); v3 = softplusf(v3); }
            }
            if (MODE == 0 || MODE == 2) {
                float* p0 = C + (size_t)(bm + row) * ldc + bn + col;
                float* p1 = C + (size_t)(bm + row + 8) * ldc + bn + col;
                *(float2*)p0 = make_float2(v0, v1);
                *(float2*)p1 = make_float2(v2, v3);
            }
            if (EMIT && (MODE != 3 || bn < 512)) {
                uint32_t h0, l0, h1, l1;
                bsplit2(v0, v1, h0, l0);
                bsplit2(v2, v3, h1, l1);
                const size_t o0 = (size_t)(bm + row) * ldoP + ((bn + col) >> 1);
                const size_t o1 = (size_t)(bm + row + 8) * ldoP + ((bn + col) >> 1);
                Oh[o0] = h0; Ol[o0] = l0;
                Oh[o1] = h1; Ol[o1] = l1;
            }
            if (MODE == 1 || MODE == 2 || (MODE == 3 && bn >= 512)) {
                float w0 = v0, w1 = v1, w2 = v2, w3 = v3;
                if (MODE == 3) { w0 = fsilu(w0); w1 = fsilu(w1); w2 = fsilu(w2); w3 = fsilu(w3); }
                const int coff = (MODE == 3) ? (bn - 512) : bn;
                float* q0 = Ct + (size_t)(coff + col) * M + bm + row;
                float* q1 = Ct + (size_t)(coff + col + 1) * M + bm + row;
                q0[0] = w0; q1[0] = w1; q0[8] = w2; q1[8] = w3;
            }
        }
    }
}

// ---------------- bc projection -> bcT [32][BT] ----------------
__global__ __launch_bounds__(256)
void bc_kernel(const float* __restrict__ xc, const float* __restrict__ w,
               const float* __restrict__ bias, float* __restrict__ bcT)
{
    __shared__ float srow[8][512];
    __shared__ float sbc[8][33];
    const int warp = threadIdx.x >> 5, lane = threadIdx.x & 31;
    const int r0 = blockIdx.x * 8, r = r0 + warp;
    const float* xr = xc + (size_t)r * INNER;
    for (int k = lane; k < INNER; k += 32) srow[warp][k] = xr[k];
    __syncwarp();
    float acc = bias[lane];
#pragma unroll 4
    for (int k = 0; k < INNER; k++)
        acc = fmaf(srow[warp][k], w[k * 32 + lane], acc);
    sbc[warp][lane] = acc;
    __syncthreads();
    const int j = threadIdx.x >> 3, rr = threadIdx.x & 7;
    bcT[(size_t)j * BT + r0 + rr] = sbc[rr][j];
}

// ---------------- chunked scan; emits split yg [kp][bt] (coalesced) --------
__global__ __launch_bounds__(256)
void scan_kernel(const float* __restrict__ xcT, const float* __restrict__ dtT,
                 const float* __restrict__ bcT, const float* __restrict__ A_log,
                 const float* __restrict__ gT,
                 uint32_t* __restrict__ ygh, uint32_t* __restrict__ ygl)
{
    __shared__ float sbc[32][292];
    const int lane = threadIdx.x & 31, warp = threadIdx.x >> 5;
    const int s = lane & 15, half = lane >> 4;
    const int b = blockIdx.y, c = blockIdx.z;
    const int d = blockIdx.x * 16 + warp * 2 + half;
    const int kp = blockIdx.x * 8 + warp;

    const int tout = c * CHUNK;
    const int off0 = (c > 0) ? tout - WARM : tout;
    const int len  = (c > 0) ? CHUNK + WARM : CHUNK;
    {
        const float* src = bcT + (size_t)b * TN + off0;
        const int q4 = len >> 2;
        for (int i = threadIdx.x; i < 32 * q4; i += 256) {
            const int r = i / q4, j = i - r * q4;
            *(float4*)&sbc[r][4 * j] = *(const float4*)(src + (size_t)r * BT + 4 * j);
        }
    }
    const float As = -__expf(A_log[d * SN + s]);
    const size_t dbase = (size_t)d * BT + (size_t)b * TN;
    __syncthreads();

    float h = 0.f;
    if (c > 0) {
        const int tw = tout - WARM;
        const float4* dtw = (const float4*)(dtT + dbase + tw);
        const float4* xcw = (const float4*)(xcT + dbase + tw);
#pragma unroll
        for (int i = 0; i < WARM / 4; i++) {
            const float4 dt4 = dtw[i], xc4 = xcw[i];
            const float4 B4 = *(const float4*)&sbc[s][4 * i];
            h = fmaf(__expf(dt4.x * As), h, dt4.x * xc4.x * B4.x);
            h = fmaf(__expf(dt4.y * As), h, dt4.y * xc4.y * B4.y);
            h = fmaf(__expf(dt4.z * As), h, dt4.z * xc4.z * B4.z);
            h = fmaf(__expf(dt4.w * As), h, dt4.w * xc4.w * B4.w);
        }
    }
    const int base = (c > 0) ? WARM : 0;
    const float4* dt4p = (const float4*)(dtT + dbase + tout);
    const float4* xc4p = (const float4*)(xcT + dbase + tout);
    const float4* g4p  = (const float4*)(gT  + dbase + tout);

    for (int i = 0; i < CHUNK / 4; i++) {
        const float4 dt4 = dt4p[i], xc4 = xc4p[i];
        const float4 B4 = *(const float4*)&sbc[s][base + 4 * i];
        const float4 C4 = *(const float4*)&sbc[16 + s][base + 4 * i];
        const float e0 = __expf(dt4.x * As);
        const float e1 = __expf(dt4.y * As);
        const float e2 = __expf(dt4.z * As);
        const float e3 = __expf(dt4.w * As);
        h = fmaf(e0, h, dt4.x * xc4.x * B4.x); float y0 = h * C4.x;
        h = fmaf(e1, h, dt4.y * xc4.y * B4.y); float y1 = h * C4.y;
        h = fmaf(e2, h, dt4.z * xc4.z * B4.z); float y2 = h * C4.z;
        h = fmaf(e3, h, dt4.w * xc4.w * B4.w); float y3 = h * C4.w;
#pragma unroll
        for (int o = 1; o <= 8; o <<= 1) {
            y0 += __shfl_xor_sync(0xffffffffu, y0, o);
            y1 += __shfl_xor_sync(0xffffffffu, y1, o);
            y2 += __shfl_xor_sync(0xffffffffu, y2, o);
            y3 += __shfl_xor_sync(0xffffffffu, y3, o);
        }
        const float4 g4 = g4p[i];
        const float z0 = y0 * g4.x, z1 = y1 * g4.y, z2 = y2 * g4.z, z3 = y3 * g4.w;
        const float p0 = __shfl_xor_sync(0xffffffffu, z0, 16);
        const float p1 = __shfl_xor_sync(0xffffffffu, z1, 16);
        const float p2 = __shfl_xor_sync(0xffffffffu, z2, 16);
        const float p3 = __shfl_xor_sync(0xffffffffu, z3, 16);
        if (lane == 0) {
            uint4 hv, lv;
            bsplit2(z0, p0, hv.x, lv.x);
            bsplit2(z1, p1, hv.y, lv.y);
            bsplit2(z2, p2, hv.z, lv.z);
            bsplit2(z3, p3, hv.w, lv.w);
            const size_t o = (size_t)kp * BT + (size_t)b * TN + tout + 4 * i;
            *(uint4*)(ygh + o) = hv;
            *(uint4*)(ygl + o) = lv;
        }
    }
}

// ---------------- catastrophe + E8 ----------------
__global__ __launch_bounds__(256)
void epi_kernel(const float* __restrict__ y,
                const float* __restrict__ cat1_w, const float* __restrict__ cat1_b,
                const float* __restrict__ cat2_w, const float* __restrict__ cat2_b,
                const float* __restrict__ risk_w, const float* __restrict__ risk_b,
                const float* __restrict__ e8a_w,  const float* __restrict__ e8a_b,
                const float* __restrict__ e8b_w,  const float* __restrict__ e8b_b,
                const float* __restrict__ cb,
                float* __restrict__ e8_out, float* __restrict__ idx_out,
                float* __restrict__ bif_out)
{
    __shared__ float sy[8][256];
    __shared__ float sf[8][64];
    __shared__ float se[8][8];
    const int warp = threadIdx.x >> 5, lane = threadIdx.x & 31;
    const int r = blockIdx.x * 8 + warp;
    const int t = r & (TN - 1);
    const float* yr = y + (size_t)r * DN;
    for (int k = lane; k < DN; k += 32) sy[warp][k] = yr[k];
    __syncwarp();

    float s1 = 0.f, s2 = 0.f;
    if (t > 0) {
        const float* yp1 = yr - DN;
        for (int k = lane; k < DN; k += 32) {
            float dv = sy[warp][k] - yp1[k];
            s1 = fmaf(dv, dv, s1);
        }
        if (t > 1) {
            const float* yp2 = yr - 2 * DN;
            for (int k = lane; k < DN; k += 32) {
                float dv = yp1[k] - yp2[k];
                s2 = fmaf(dv, dv, s2);
            }
        }
    }
#pragma unroll
    for (int o = 16; o; o >>= 1) {
        s1 += __shfl_xor_sync(0xffffffffu, s1, o);
        s2 += __shfl_xor_sync(0xffffffffu, s2, o);
    }
    const float vn = sqrtf(s1), vnp = sqrtf(s2);
    const float accv = fabsf(vn - vnp);

    float f1a = cat1_b[lane], f1b = cat1_b[lane + 32];
    float e1a = e8a_b[lane],  e1b = e8a_b[lane + 32];
#pragma unroll 4
    for (int k = 0; k < DN; k++) {
        const float yv = sy[warp][k];
        f1a = fmaf(yv, cat1_w[k * 64 + lane], f1a);
        f1b = fmaf(yv, cat1_w[k * 64 + lane + 32], f1b);
        e1a = fmaf(yv, e8a_w[k * 64 + lane], e1a);
        e1b = fmaf(yv, e8a_w[k * 64 + lane + 32], e1b);
    }
    f1a = geluf(f1a); f1b = geluf(f1b);
    e1a = geluf(e1a); e1b = geluf(e1b);
    sf[warp][lane] = f1a; sf[warp][lane + 32] = f1b;
    __syncwarp();

    float f2 = cat2_b[lane];
#pragma unroll 8
    for (int k = 0; k < 64; k++)
        f2 = fmaf(sf[warp][k], cat2_w[k * 32 + lane], f2);
    float rp = f2 * risk_w[lane];
#pragma unroll
    for (int o = 16; o; o >>= 1) rp += __shfl_xor_sync(0xffffffffu, rp, o);
    const float risk = sigf(rp + risk_b[0]);
    const float combined = 0.5f * risk + 0.3f * sigf(vn) + 0.2f * sigf(accv);
    if (lane == 0) bif_out[r] = combined > 0.7f ? 1.f : 0.f;

    __syncwarp();
    sf[warp][lane] = e1a; sf[warp][lane + 32] = e1b;
    __syncwarp();
    float e8c = 0.f;
    if (lane < 8) {
        e8c = e8b_b[lane];
#pragma unroll 8
        for (int k = 0; k < 64; k++)
            e8c = fmaf(sf[warp][k], e8b_w[k * 8 + lane], e8c);
        se[warp][lane] = e8c;
    }
    __syncwarp();
    float fn2 = (lane < 8) ? e8c * e8c : 0.f;
#pragma unroll
    for (int o = 16; o; o >>= 1) fn2 += __shfl_xor_sync(0xffffffffu, fn2, o);

    const float f0 = se[warp][0], f1 = se[warp][1], f2v = se[warp][2], f3 = se[warp][3];
    const float f4 = se[warp][4], f5 = se[warp][5], f6v = se[warp][6], f7 = se[warp][7];
    float best = FLT_MAX;
    int bidx = 0x7fffffff;
    for (int c = lane; c < NCODE; c += 32) {
        const float* cp = cb + c * 8;
        float dot = f0*cp[0] + f1*cp[1] + f2v*cp[2] + f3*cp[3]
                  + f4*cp[4] + f5*cp[5] + f6v*cp[6] + f7*cp[7];
        float cn2 = cp[0]*cp[0] + cp[1]*cp[1] + cp[2]*cp[2] + cp[3]*cp[3]
                  + cp[4]*cp[4] + cp[5]*cp[5] + cp[6]*cp[6] + cp[7]*cp[7];
        float d2 = fn2 - 2.f * dot + cn2;
        if (d2 < best) { best = d2; bidx = c; }
    }
#pragma unroll
    for (int o = 16; o; o >>= 1) {
        float ob = __shfl_xor_sync(0xffffffffu, best, o);
        int   oi = __shfl_xor_sync(0xffffffffu, bidx, o);
        if (ob < best || (ob == best && oi < bidx)) { best = ob; bidx = oi; }
    }
    if (lane < 8) {
        const float qv = cb[bidx * 8 + lane];
        const float ec = se[warp][lane];
        e8_out[(size_t)r * 8 + lane] = ec + (qv - ec);
    }
    if (lane == 0) idx_out[r] = (float)bidx;
}

// ---------------- launcher ----------------
extern "C" void kernel_launch(void* const* d_in, const int* in_sizes, int n_in,
                              void* d_out, int out_size)
{
    const float* x         = (const float*)d_in[0];
    const float* in_proj_w = (const float*)d_in[1];
    const float* in_proj_b = (const float*)d_in[2];
    const float* conv_w    = (const float*)d_in[3];
    const float* conv_b    = (const float*)d_in[4];
    const float* A_log     = (const float*)d_in[5];
    const float* bc_w      = (const float*)d_in[6];
    const float* bc_b      = (const float*)d_in[7];
    const float* dt_w      = (const float*)d_in[8];
    const float* dt_b      = (const float*)d_in[9];
    const float* out_w     = (const float*)d_in[10];
    const float* out_b     = (const float*)d_in[11];
    const float* cat1_w    = (const float*)d_in[12];
    const float* cat1_b    = (const float*)d_in[13];
    const float* cat2_w    = (const float*)d_in[14];
    const float* cat2_b    = (const float*)d_in[15];
    const float* risk_w    = (const float*)d_in[16];
    const float* risk_b    = (const float*)d_in[17];
    const float* e8a_w     = (const float*)d_in[18];
    const float* e8a_b     = (const float*)d_in[19];
    const float* e8b_w     = (const float*)d_in[20];
    const float* e8b_b     = (const float*)d_in[21];
    const float* cbk       = (const float*)d_in[22];

    float* out = (float*)d_out;
    float* y_out   = out;
    float* e8_out  = out + (size_t)BT * DN;
    float* idx_out = out + (size_t)BT * DN + (size_t)BT * 8;
    float* bif_out = idx_out + BT;

    float *gT, *xc, *xcT, *dtT, *bcT;
    uint32_t *xsh, *xsl, *xmh, *xml, *xch, *xcl, *ygh, *ygl;
    uint32_t *w1h, *w1l, *w2h, *w2l, *w3h, *w3l, *w4h, *w4l;
    cudaGetSymbolAddress((void**)&gT, g_gT);
    cudaGetSymbolAddress((void**)&xc, g_xc);
    cudaGetSymbolAddress((void**)&xcT, g_xcT);
    cudaGetSymbolAddress((void**)&dtT, g_dtT);
    cudaGetSymbolAddress((void**)&bcT, g_bcT);
    cudaGetSymbolAddress((void**)&xsh, g_xsh);
    cudaGetSymbolAddress((void**)&xsl, g_xsl);
    cudaGetSymbolAddress((void**)&xmh, g_xmh);
    cudaGetSymbolAddress((void**)&xml, g_xml);
    cudaGetSymbolAddress((void**)&xch, g_xch);
    cudaGetSymbolAddress((void**)&xcl, g_xcl);
    cudaGetSymbolAddress((void**)&ygh, g_ygh);
    cudaGetSymbolAddress((void**)&ygl, g_ygl);
    cudaGetSymbolAddress((void**)&w1h, g_w1h);
    cudaGetSymbolAddress((void**)&w1l, g_w1l);
    cudaGetSymbolAddress((void**)&w2h, g_w2h);
    cudaGetSymbolAddress((void**)&w2l, g_w2l);
    cudaGetSymbolAddress((void**)&w3h, g_w3h);
    cudaGetSymbolAddress((void**)&w3l, g_w3l);
    cudaGetSymbolAddress((void**)&w4h, g_w4h);
    cudaGetSymbolAddress((void**)&w4l, g_w4l);

    cudaFuncSetAttribute(tgemm<0,3,false,true,false>,  cudaFuncAttributeMaxDynamicSharedMemorySize, SMEMB);
    cudaFuncSetAttribute(tgemm<1,2,false,true,false>,  cudaFuncAttributeMaxDynamicSharedMemorySize, SMEMB);
    cudaFuncSetAttribute(tgemm<2,1,false,false,false>, cudaFuncAttributeMaxDynamicSharedMemorySize, SMEMB);
    cudaFuncSetAttribute(tgemm<0,1,true,false,true>,   cudaFuncAttributeMaxDynamicSharedMemorySize, SMEMB);

    // 0) prep
    wprepB<<<(1024 * 128 + 255) / 256, 256>>>(in_proj_w, w1h, w1l, 1024, 128);
    wprepB<<<(512 * 256 + 255) / 256, 256>>>(conv_w, w2h, w2l, 512, 256);
    wprepB<<<(512 * 256 + 255) / 256, 256>>>(dt_w, w3h, w3l, 512, 256);
    wprepT<<<(256 * 256 + 255) / 256, 256>>>(out_w, w4h, w4l, 256, 256);
    xsplit<<<BT * 128 / 256, 256>>>(x, xsh, xsl);

    // 1) in_proj: bn<512 emit split xmain; bn>=512 gT (silu, transposed)
    tgemm<0,3,false,true,false><<<dim3(8, BT / 128), 256, SMEMB>>>(
        xsh, xsl, 128, w1h, w1l, 128, in_proj_b,
        nullptr, 0, gT, xmh, xml, 256, 256);
    // 2) conv: silu; xc fp32 + xcT + emit split xc
    tgemm<1,2,false,true,false><<<dim3(4, BT / 128), 256, SMEMB>>>(
        xmh, xml, 256, w2h, w2l, 256, conv_b,
        xc, INNER, xcT, xch, xcl, 256, 512);
    // 3) bc -> bcT
    bc_kernel<<<BT / 8, 256>>>(xc, bc_w, bc_b, bcT);
    // 4) dt: softplus -> dtT (transposed)
    tgemm<2,1,false,false,false><<<dim3(4, BT / 128), 256, SMEMB>>>(
        xch, xcl, 256, w3h, w3l, 256, dt_b,
        nullptr, 0, dtT, nullptr, nullptr, 0, 512);
    // 5) scan (+gate) -> split yg [kp][bt] (coalesced)
    scan_kernel<<<dim3(INNER / 16, BN, NCHUNK), 256>>>(xcT, dtT, bcT, A_log, gT, ygh, ygl);
    // 6) out_proj: w4^T (A, ldmatrix) @ yg (B k-major, BKM) -> y_out[bt][j]
    tgemm<0,1,true,false,true><<<dim3(BT / 128, 2), 256, SMEMB>>>(
        w4h, w4l, 256, ygh, ygl, BT, out_b,
        nullptr, 0, y_out, nullptr, nullptr, 0, 512);
    // 7) catastrophe + E8
    epi_kernel<<<BT / 8, 256>>>(y_out, cat1_w, cat1_b, cat2_w, cat2_b,
                                risk_w, risk_b, e8a_w, e8a_b, e8b_w, e8b_b,
                                cbk, e8_out, idx_out, bif_out);
}

// round 13
// speedup vs baseline: 1.1351x; 1.1351x over previous
#include <cuda_runtime.h>
#include <cuda_bf16.h>
#include <math.h>
#include <float.h>
#include <stdint.h>

#define BN 8
#define TN 4096
#define DN 256
#define INNER 512
#define SN 16
#define BT 32768
#define NCODE 240
#define CHUNK 256
#define WARM 32
#define NCHUNK (TN / CHUNK)

// ---------------- scratch ----------------
__device__ float g_gT[(size_t)INNER * BT];
__device__ float g_xc[(size_t)BT * INNER];
__device__ float g_xcT[(size_t)INNER * BT];
__device__ float g_dtT[(size_t)INNER * BT];
__device__ float g_bcT[(size_t)32 * BT];
__device__ uint32_t g_xsh[(size_t)BT * 128], g_xsl[(size_t)BT * 128];
__device__ uint32_t g_xmh[(size_t)BT * 256], g_xml[(size_t)BT * 256];
__device__ uint32_t g_xch[(size_t)BT * 256], g_xcl[(size_t)BT * 256];
__device__ uint32_t g_ygh[(size_t)256 * BT], g_ygl[(size_t)256 * BT];   // [kp][bt]
__device__ uint32_t g_w1h[131072], g_w1l[131072];  // [n=1024][kp=128]
__device__ uint32_t g_w2h[131072], g_w2l[131072];  // [n=512][kp=256]
__device__ uint32_t g_w3h[131072], g_w3l[131072];  // [n=512][kp=256]
__device__ uint32_t g_w4h[65536],  g_w4l[65536];   // out_w^T [m=256][kp=256]

// ---------------- math ----------------
__device__ __forceinline__ float fexp(float x) {
    float t = x * 1.4426950408889634f;
    t = fminf(fmaxf(t, -100.f), 100.f);
    float z = t + 12582912.0f;
    int n = __float_as_int(z) - 0x4B400000;
    float r = t - (z - 12582912.0f);
    float p = 1.5403530394e-4f;
    p = fmaf(p, r, 1.3333558146e-3f);
    p = fmaf(p, r, 9.6181291076e-3f);
    p = fmaf(p, r, 5.5504108664e-2f);
    p = fmaf(p, r, 2.4022650696e-1f);
    p = fmaf(p, r, 6.9314718056e-1f);
    p = fmaf(p, r, 1.0f);
    return __int_as_float(__float_as_int(p) + (n << 23));
}
__device__ __forceinline__ float frcp_fast(float x) {
    float r = __uint_as_float(0x7EF311C3u - __float_as_uint(x));
    r = r * (2.f - x * r); r = r * (2.f - x * r); r = r * (2.f - x * r);
    return r;
}
__device__ __forceinline__ float fsig(float x)  { return frcp_fast(1.f + fexp(-x)); }
__device__ __forceinline__ float fsilu(float x) { return x * fsig(x); }
__device__ __forceinline__ float sigf(float x)  { return 1.f / (1.f + __expf(-x)); }
__device__ __forceinline__ float softplusf(float x) {
    return x > 20.f ? x : __logf(1.f + fexp(x));
}
__device__ __forceinline__ float geluf(float x) {
    const float c = 0.7978845608028654f;
    float t = tanhf(c * (x + 0.044715f * x * x * x));
    return 0.5f * x * (1.f + t);
}
__device__ __forceinline__ void bsplit2(float f0, float f1, uint32_t& hi, uint32_t& lo) {
    __nv_bfloat16 h0 = __float2bfloat16_rn(f0);
    __nv_bfloat16 h1 = __float2bfloat16_rn(f1);
    __nv_bfloat162 hh; hh.x = h0; hh.y = h1;
    hi = *reinterpret_cast<uint32_t*>(&hh);
    __nv_bfloat162 ll = __floats2bfloat162_rn(f0 - __bfloat162float(h0),
                                              f1 - __bfloat162float(h1));
    lo = *reinterpret_cast<uint32_t*>(&ll);
}
__device__ __forceinline__ void mma_bf16(float c[4], const uint32_t a[4], const uint32_t b[2]) {
    asm volatile(
        "mma.sync.aligned.m16n8k16.row.col.f32.bf16.bf16.f32 "
        "{%0,%1,%2,%3}, {%4,%5,%6,%7}, {%8,%9}, {%0,%1,%2,%3};\n"
        : "+f"(c[0]), "+f"(c[1]), "+f"(c[2]), "+f"(c[3])
        : "r"(a[0]), "r"(a[1]), "r"(a[2]), "r"(a[3]), "r"(b[0]), "r"(b[1]));
}
__device__ __forceinline__ void ldsm4(uint32_t& r0, uint32_t& r1, uint32_t& r2,
                                      uint32_t& r3, uint32_t addr) {
    asm volatile("ldmatrix.sync.aligned.m8n8.x4.shared.b16 {%0,%1,%2,%3}, [%4];"
                 : "=r"(r0), "=r"(r1), "=r"(r2), "=r"(r3) : "r"(addr));
}
__device__ __forceinline__ void cp16(uint32_t s, const void* g) {
    asm volatile("cp.async.cg.shared.global [%0], [%1], 16;\n" :: "r"(s), "l"(g));
}
__device__ __forceinline__ void cp_commit() { asm volatile("cp.async.commit_group;\n"); }
__device__ __forceinline__ void cp_wait1()  { asm volatile("cp.async.wait_group 1;\n"); }

// ---------------- fused prep: all weight splits + x split in ONE launch ----
__global__ __launch_bounds__(256)
void prep_all(const float* __restrict__ x, const float* __restrict__ w1,
              const float* __restrict__ w2, const float* __restrict__ w3,
              const float* __restrict__ w4,
              uint32_t* __restrict__ xsh, uint32_t* __restrict__ xsl,
              uint32_t* __restrict__ w1h, uint32_t* __restrict__ w1l,
              uint32_t* __restrict__ w2h, uint32_t* __restrict__ w2l,
              uint32_t* __restrict__ w3h, uint32_t* __restrict__ w3l,
              uint32_t* __restrict__ w4h, uint32_t* __restrict__ w4l)
{
    size_t i = (size_t)blockIdx.x * 256 + threadIdx.x;
    const size_t NX = (size_t)BT * 128;
    if (i < NX) {
        float2 v = *(const float2*)(x + 2 * i);
        bsplit2(v.x, v.y, xsh[i], xsl[i]);
        return;
    }
    i -= NX;
    if (i < 131072) {                       // w1 [n=1024][kp=128]
        int n = (int)(i >> 7), kp = (int)(i & 127);
        bsplit2(w1[(size_t)(2 * kp) * 1024 + n], w1[(size_t)(2 * kp + 1) * 1024 + n],
                w1h[i], w1l[i]);
        return;
    }
    i -= 131072;
    if (i < 131072) {                       // w2 [n=512][kp=256]
        int n = (int)(i >> 8), kp = (int)(i & 255);
        bsplit2(w2[(size_t)(2 * kp) * 512 + n], w2[(size_t)(2 * kp + 1) * 512 + n],
                w2h[i], w2l[i]);
        return;
    }
    i -= 131072;
    if (i < 131072) {                       // w3 [n=512][kp=256]
        int n = (int)(i >> 8), kp = (int)(i & 255);
        bsplit2(w3[(size_t)(2 * kp) * 512 + n], w3[(size_t)(2 * kp + 1) * 512 + n],
                w3h[i], w3l[i]);
        return;
    }
    i -= 131072;
    if (i < 65536) {                        // w4^T [m=256][kp=256]
        int m = (int)(i >> 8), kp = (int)(i & 255);
        bsplit2(w4[(size_t)(2 * kp) * 256 + m], w4[(size_t)(2 * kp + 1) * 256 + m],
                w4h[i], w4l[i]);
    }
}
#define PREP_TOTAL ((size_t)BT * 128 + 131072 * 3 + 65536)

// ---------------- bf16x3 GEMM (round-12 state: cp.async ring + ldmatrix) ---
#define PITCH 12
#define BPITCH 136
#define TSTG  (128 * PITCH)
#define SMEMB (12 * TSTG * 4)

template <int EPI, int MODE, bool BROW, bool EMIT, bool BKM>
__global__ __launch_bounds__(256)
void tgemm(const uint32_t* __restrict__ Ah, const uint32_t* __restrict__ Al, int ldaP,
           const uint32_t* __restrict__ Bh, const uint32_t* __restrict__ Bl, int ldbP,
           const float* __restrict__ bias,
           float* __restrict__ C, int ldc, float* __restrict__ Ct,
           uint32_t* __restrict__ Oh, uint32_t* __restrict__ Ol, int ldoP, int K)
{
    extern __shared__ uint32_t smq[];
    const int tid = threadIdx.x, lane = tid & 31, warp = tid >> 5;
    const int wm = warp >> 2, wn = warp & 3;
    const int bm = blockIdx.y * 128, bn = blockIdx.x * 128;
    const int M = gridDim.y * 128;

    const int ar = tid >> 1, ap = (tid & 1) << 2;
    const uint32_t smem0 = (uint32_t)__cvta_generic_to_shared(smq);
    const uint32_t awrd = smem0 + (uint32_t)(ar * PITCH + ap) * 4;
    const uint32_t bwrd_km = smem0 + (uint32_t)(warp * BPITCH + (lane << 2)) * 4;

    const uint32_t* Agh = Ah + (size_t)(bm + ar) * ldaP + ap;
    const uint32_t* Agl = Al + (size_t)(bm + ar) * ldaP + ap;
    const uint32_t* Bgh;
    const uint32_t* Bgl;
    if (BKM) {
        Bgh = Bh + (size_t)warp * ldbP + bn + (lane << 2);
        Bgl = Bl + (size_t)warp * ldbP + bn + (lane << 2);
    } else {
        Bgh = Bh + (size_t)(bn + ar) * ldbP + ap;
        Bgl = Bl + (size_t)(bn + ar) * ldbP + ap;
    }

    const uint32_t aoff = (uint32_t)(((wm * 64 + ((lane >> 3) & 1) * 8 + (lane & 7)) * PITCH
                                      + (lane >> 4) * 4) * 4);
    const uint32_t boff = (uint32_t)(((wn * 32 + ((lane >> 4) & 1) * 8 + (lane & 7)) * PITCH
                                      + ((lane >> 3) & 1) * 4) * 4);

    const int NT = K >> 4;
    float acc[4][4][4];
#pragma unroll
    for (int i = 0; i < 4; i++)
#pragma unroll
        for (int j = 0; j < 4; j++)
#pragma unroll
            for (int r = 0; r < 4; r++) acc[i][j][r] = 0.f;

    auto load_tile = [&](int t, int st) {
        const int kp0 = t * 8;
        cp16(awrd + (uint32_t)((st * 4 + 0) * TSTG) * 4, Agh + kp0);
        cp16(awrd + (uint32_t)((st * 4 + 1) * TSTG) * 4, Agl + kp0);
        if (BKM) {
            cp16(bwrd_km + (uint32_t)((st * 4 + 2) * TSTG) * 4, Bgh + (size_t)kp0 * ldbP);
            cp16(bwrd_km + (uint32_t)((st * 4 + 3) * TSTG) * 4, Bgl + (size_t)kp0 * ldbP);
        } else {
            cp16(awrd + (uint32_t)((st * 4 + 2) * TSTG) * 4, Bgh + kp0);
            cp16(awrd + (uint32_t)((st * 4 + 3) * TSTG) * 4, Bgl + kp0);
        }
    };
    load_tile(0, 0); cp_commit();
    load_tile(1, 1); cp_commit();

    const int tig = lane & 3, gid = lane >> 2;
    int st = 0;
    for (int i = 0; i < NT; i++) {
        cp_wait1();
        __syncthreads();
        int stn = st + 2; if (stn >= 3) stn -= 3;
        if (i + 2 < NT) load_tile(i + 2, stn);
        cp_commit();

        const uint32_t bAh = smem0 + (uint32_t)((st * 4 + 0) * TSTG) * 4;
        const uint32_t bAl = smem0 + (uint32_t)((st * 4 + 1) * TSTG) * 4;

        uint32_t afh[4][4], afl[4][4], bfh[4][2], bfl[4][2];
#pragma unroll
        for (int mf = 0; mf < 4; mf++) {
            ldsm4(afh[mf][0], afh[mf][1], afh[mf][2], afh[mf][3], bAh + aoff + mf * (16 * PITCH * 4));
            ldsm4(afl[mf][0], afl[mf][1], afl[mf][2], afl[mf][3], bAl + aoff + mf * (16 * PITCH * 4));
        }
        if (BKM) {
            const uint32_t* Bsh = smq + (st * 4 + 2) * TSTG;
            const uint32_t* Bsl = smq + (st * 4 + 3) * TSTG;
#pragma unroll
            for (int nf = 0; nf < 4; nf++) {
                const int nn = wn * 32 + nf * 8 + gid;
                bfh[nf][0] = Bsh[tig * BPITCH + nn];
                bfh[nf][1] = Bsh[(tig + 4) * BPITCH + nn];
                bfl[nf][0] = Bsl[tig * BPITCH + nn];
                bfl[nf][1] = Bsl[(tig + 4) * BPITCH + nn];
            }
        } else {
            const uint32_t bBh = smem0 + (uint32_t)((st * 4 + 2) * TSTG) * 4;
            const uint32_t bBl = smem0 + (uint32_t)((st * 4 + 3) * TSTG) * 4;
#pragma unroll
            for (int p = 0; p < 2; p++) {
                ldsm4(bfh[2 * p][0], bfh[2 * p][1], bfh[2 * p + 1][0], bfh[2 * p + 1][1],
                      bBh + boff + p * (16 * PITCH * 4));
                ldsm4(bfl[2 * p][0], bfl[2 * p][1], bfl[2 * p + 1][0], bfl[2 * p + 1][1],
                      bBl + boff + p * (16 * PITCH * 4));
            }
        }
#pragma unroll
        for (int mf = 0; mf < 4; mf++)
#pragma unroll
            for (int nf = 0; nf < 4; nf++)
                mma_bf16(acc[mf][nf], afl[mf], bfh[nf]);
#pragma unroll
        for (int mf = 0; mf < 4; mf++)
#pragma unroll
            for (int nf = 0; nf < 4; nf++)
                mma_bf16(acc[mf][nf], afh[mf], bfl[nf]);
#pragma unroll
        for (int mf = 0; mf < 4; mf++)
#pragma unroll
            for (int nf = 0; nf < 4; nf++)
                mma_bf16(acc[mf][nf], afh[mf], bfh[nf]);

        st = (st + 1 == 3) ? 0 : st + 1;
    }

#pragma unroll
    for (int mf = 0; mf < 4; mf++) {
#pragma unroll
        for (int nf = 0; nf < 4; nf++) {
            const int col = wn * 32 + nf * 8 + tig * 2;
            const int row = wm * 64 + mf * 16 + gid;
            float b0, b1, b2, b3;
            if (BROW) { b0 = b1 = bias[bm + row]; b2 = b3 = bias[bm + row + 8]; }
            else      { b0 = b2 = bias[bn + col]; b1 = b3 = bias[bn + col + 1]; }
            float v0 = acc[mf][nf][0] + b0;
            float v1 = acc[mf][nf][1] + b1;
            float v2 = acc[mf][nf][2] + b2;
            float v3 = acc[mf][nf][3] + b3;
            if (MODE != 3) {
                if (EPI == 1) { v0 = fsilu(v0); v1 = fsilu(v1); v2 = fsilu(v2); v3 = fsilu(v3); }
                else if (EPI == 2) { v0 = softplusf(v0); v1 = softplusf(v1); v2 = softplusf(v2); v3 = softplusf(v3); }
            }
            if (MODE == 0 || MODE == 2) {
                float* p0 = C + (size_t)(bm + row) * ldc + bn + col;
                float* p1 = C + (size_t)(bm + row + 8) * ldc + bn + col;
                *(float2*)p0 = make_float2(v0, v1);
                *(float2*)p1 = make_float2(v2, v3);
            }
            if (EMIT && (MODE != 3 || bn < 512)) {
                uint32_t h0, l0, h1, l1;
                bsplit2(v0, v1, h0, l0);
                bsplit2(v2, v3, h1, l1);
                const size_t o0 = (size_t)(bm + row) * ldoP + ((bn + col) >> 1);
                const size_t o1 = (size_t)(bm + row + 8) * ldoP + ((bn + col) >> 1);
                Oh[o0] = h0; Ol[o0] = l0;
                Oh[o1] = h1; Ol[o1] = l1;
            }
            if (MODE == 1 || MODE == 2 || (MODE == 3 && bn >= 512)) {
                float w0 = v0, w1 = v1, w2 = v2, w3 = v3;
                if (MODE == 3) { w0 = fsilu(w0); w1 = fsilu(w1); w2 = fsilu(w2); w3 = fsilu(w3); }
                const int coff = (MODE == 3) ? (bn - 512) : bn;
                float* q0 = Ct + (size_t)(coff + col) * M + bm + row;
                float* q1 = Ct + (size_t)(coff + col + 1) * M + bm + row;
                q0[0] = w0; q1[0] = w1; q0[8] = w2; q1[8] = w3;
            }
        }
    }
}

// ---------------- bc projection -> bcT [32][BT] ----------------
__global__ __launch_bounds__(256)
void bc_kernel(const float* __restrict__ xc, const float* __restrict__ w,
               const float* __restrict__ bias, float* __restrict__ bcT)
{
    __shared__ float srow[8][512];
    __shared__ float sbc[8][33];
    const int warp = threadIdx.x >> 5, lane = threadIdx.x & 31;
    const int r0 = blockIdx.x * 8, r = r0 + warp;
    const float* xr = xc + (size_t)r * INNER;
    for (int k = lane; k < INNER; k += 32) srow[warp][k] = xr[k];
    __syncwarp();
    float acc = bias[lane];
#pragma unroll 4
    for (int k = 0; k < INNER; k++)
        acc = fmaf(srow[warp][k], w[k * 32 + lane], acc);
    sbc[warp][lane] = acc;
    __syncthreads();
    const int j = threadIdx.x >> 3, rr = threadIdx.x & 7;
    bcT[(size_t)j * BT + r0 + rr] = sbc[rr][j];
}

// ---------------- chunked scan; emits split yg [kp][bt] (coalesced) --------
__global__ __launch_bounds__(256)
void scan_kernel(const float* __restrict__ xcT, const float* __restrict__ dtT,
                 const float* __restrict__ bcT, const float* __restrict__ A_log,
                 const float* __restrict__ gT,
                 uint32_t* __restrict__ ygh, uint32_t* __restrict__ ygl)
{
    __shared__ float sbc[32][292];
    const int lane = threadIdx.x & 31, warp = threadIdx.x >> 5;
    const int s = lane & 15, half = lane >> 4;
    const int b = blockIdx.y, c = blockIdx.z;
    const int d = blockIdx.x * 16 + warp * 2 + half;
    const int kp = blockIdx.x * 8 + warp;

    const int tout = c * CHUNK;
    const int off0 = (c > 0) ? tout - WARM : tout;
    const int len  = (c > 0) ? CHUNK + WARM : CHUNK;
    {
        const float* src = bcT + (size_t)b * TN + off0;
        const int q4 = len >> 2;
        for (int i = threadIdx.x; i < 32 * q4; i += 256) {
            const int r = i / q4, j = i - r * q4;
            *(float4*)&sbc[r][4 * j] = *(const float4*)(src + (size_t)r * BT + 4 * j);
        }
    }
    const float As = -__expf(A_log[d * SN + s]);
    const size_t dbase = (size_t)d * BT + (size_t)b * TN;
    __syncthreads();

    float h = 0.f;
    if (c > 0) {
        const int tw = tout - WARM;
        const float4* dtw = (const float4*)(dtT + dbase + tw);
        const float4* xcw = (const float4*)(xcT + dbase + tw);
#pragma unroll
        for (int i = 0; i < WARM / 4; i++) {
            const float4 dt4 = dtw[i], xc4 = xcw[i];
            const float4 B4 = *(const float4*)&sbc[s][4 * i];
            h = fmaf(__expf(dt4.x * As), h, dt4.x * xc4.x * B4.x);
            h = fmaf(__expf(dt4.y * As), h, dt4.y * xc4.y * B4.y);
            h = fmaf(__expf(dt4.z * As), h, dt4.z * xc4.z * B4.z);
            h = fmaf(__expf(dt4.w * As), h, dt4.w * xc4.w * B4.w);
        }
    }
    const int base = (c > 0) ? WARM : 0;
    const float4* dt4p = (const float4*)(dtT + dbase + tout);
    const float4* xc4p = (const float4*)(xcT + dbase + tout);
    const float4* g4p  = (const float4*)(gT  + dbase + tout);

    for (int i = 0; i < CHUNK / 4; i++) {
        const float4 dt4 = dt4p[i], xc4 = xc4p[i];
        const float4 B4 = *(const float4*)&sbc[s][base + 4 * i];
        const float4 C4 = *(const float4*)&sbc[16 + s][base + 4 * i];
        const float e0 = __expf(dt4.x * As);
        const float e1 = __expf(dt4.y * As);
        const float e2 = __expf(dt4.z * As);
        const float e3 = __expf(dt4.w * As);
        h = fmaf(e0, h, dt4.x * xc4.x * B4.x); float y0 = h * C4.x;
        h = fmaf(e1, h, dt4.y * xc4.y * B4.y); float y1 = h * C4.y;
        h = fmaf(e2, h, dt4.z * xc4.z * B4.z); float y2 = h * C4.z;
        h = fmaf(e3, h, dt4.w * xc4.w * B4.w); float y3 = h * C4.w;
#pragma unroll
        for (int o = 1; o <= 8; o <<= 1) {
            y0 += __shfl_xor_sync(0xffffffffu, y0, o);
            y1 += __shfl_xor_sync(0xffffffffu, y1, o);
            y2 += __shfl_xor_sync(0xffffffffu, y2, o);
            y3 += __shfl_xor_sync(0xffffffffu, y3, o);
        }
        const float4 g4 = g4p[i];
        const float z0 = y0 * g4.x, z1 = y1 * g4.y, z2 = y2 * g4.z, z3 = y3 * g4.w;
        const float p0 = __shfl_xor_sync(0xffffffffu, z0, 16);
        const float p1 = __shfl_xor_sync(0xffffffffu, z1, 16);
        const float p2 = __shfl_xor_sync(0xffffffffu, z2, 16);
        const float p3 = __shfl_xor_sync(0xffffffffu, z3, 16);
        if (lane == 0) {
            uint4 hv, lv;
            bsplit2(z0, p0, hv.x, lv.x);
            bsplit2(z1, p1, hv.y, lv.y);
            bsplit2(z2, p2, hv.z, lv.z);
            bsplit2(z3, p3, hv.w, lv.w);
            const size_t o = (size_t)kp * BT + (size_t)b * TN + tout + 4 * i;
            *(uint4*)(ygh + o) = hv;
            *(uint4*)(ygl + o) = lv;
        }
    }
}

// ---------------- catastrophe + E8: 4 rows per warp, amortized weights -----
__global__ __launch_bounds__(256)
void epi_kernel(const float* __restrict__ y,
                const float* __restrict__ cat1_w, const float* __restrict__ cat1_b,
                const float* __restrict__ cat2_w, const float* __restrict__ cat2_b,
                const float* __restrict__ risk_w, const float* __restrict__ risk_b,
                const float* __restrict__ e8a_w,  const float* __restrict__ e8a_b,
                const float* __restrict__ e8b_w,  const float* __restrict__ e8b_b,
                const float* __restrict__ cb,
                float* __restrict__ e8_out, float* __restrict__ idx_out,
                float* __restrict__ bif_out)
{
    __shared__ float sy[32][264];
    __shared__ float sf[8][4][64];
    __shared__ float se[8][4][8];

    const int tid = threadIdx.x, warp = tid >> 5, lane = tid & 31;
    const int r0 = blockIdx.x * 32;
    const int rbase = warp * 4;

    // stage 32 y rows (coalesced)
    for (int i = tid; i < 32 * 64; i += 256) {
        const int row = i >> 6, j = i & 63;
        *(float4*)&sy[row][4 * j] = *(const float4*)(y + (size_t)(r0 + row) * DN + 4 * j);
    }
    __syncthreads();

    // ---- cat1 & e8a hidden layers: outputs (2*lane, 2*lane+1), 4 rows ----
    float f1[4][2], e1[4][2];
    {
        const float2 cb2 = *(const float2*)(cat1_b + 2 * lane);
        const float2 eb2 = *(const float2*)(e8a_b + 2 * lane);
#pragma unroll
        for (int rr = 0; rr < 4; rr++) {
            f1[rr][0] = cb2.x; f1[rr][1] = cb2.y;
            e1[rr][0] = eb2.x; e1[rr][1] = eb2.y;
        }
    }
    for (int k = 0; k < DN; k++) {
        const float2 wc = *(const float2*)(cat1_w + k * 64 + 2 * lane);
        const float2 we = *(const float2*)(e8a_w + k * 64 + 2 * lane);
#pragma unroll
        for (int rr = 0; rr < 4; rr++) {
            const float yv = sy[rbase + rr][k];
            f1[rr][0] = fmaf(yv, wc.x, f1[rr][0]);
            f1[rr][1] = fmaf(yv, wc.y, f1[rr][1]);
            e1[rr][0] = fmaf(yv, we.x, e1[rr][0]);
            e1[rr][1] = fmaf(yv, we.y, e1[rr][1]);
        }
    }
#pragma unroll
    for (int rr = 0; rr < 4; rr++) {
        sf[warp][rr][2 * lane]     = geluf(f1[rr][0]);
        sf[warp][rr][2 * lane + 1] = geluf(f1[rr][1]);
    }
    __syncwarp();

    // ---- cat2 + risk (4 rows jointly) ----
    float f2[4];
    {
        const float c2b = cat2_b[lane];
#pragma unroll
        for (int rr = 0; rr < 4; rr++) f2[rr] = c2b;
    }
    for (int k = 0; k < 64; k++) {
        const float w = cat2_w[k * 32 + lane];
#pragma unroll
        for (int rr = 0; rr < 4; rr++)
            f2[rr] = fmaf(sf[warp][rr][k], w, f2[rr]);
    }
    float rp[4];
    {
        const float rw = risk_w[lane];
#pragma unroll
        for (int rr = 0; rr < 4; rr++) rp[rr] = f2[rr] * rw;
    }
#pragma unroll
    for (int o = 16; o; o >>= 1)
#pragma unroll
        for (int rr = 0; rr < 4; rr++)
            rp[rr] += __shfl_xor_sync(0xffffffffu, rp[rr], o);
    const float rb0 = risk_b[0];

    // ---- velocity / acceleration per row (lane covers 8 consecutive k) ----
    float combined[4];
#pragma unroll
    for (int rr = 0; rr < 4; rr++) {
        const int r = r0 + rbase + rr;
        const int t = r & (TN - 1);
        float s1 = 0.f, s2 = 0.f;
        if (t > 0) {
            const int k0 = lane * 8;
            const float* yp1 = y + (size_t)(r - 1) * DN + k0;
            const float4 a0 = *(const float4*)&sy[rbase + rr][k0];
            const float4 a1 = *(const float4*)&sy[rbase + rr][k0 + 4];
            const float4 b0 = *(const float4*)(yp1);
            const float4 b1 = *(const float4*)(yp1 + 4);
            float d;
            d = a0.x - b0.x; s1 = fmaf(d, d, s1);
            d = a0.y - b0.y; s1 = fmaf(d, d, s1);
            d = a0.z - b0.z; s1 = fmaf(d, d, s1);
            d = a0.w - b0.w; s1 = fmaf(d, d, s1);
            d = a1.x - b1.x; s1 = fmaf(d, d, s1);
            d = a1.y - b1.y; s1 = fmaf(d, d, s1);
            d = a1.z - b1.z; s1 = fmaf(d, d, s1);
            d = a1.w - b1.w; s1 = fmaf(d, d, s1);
            if (t > 1) {
                const float* yp2 = y + (size_t)(r - 2) * DN + k0;
                const float4 c0 = *(const float4*)(yp2);
                const float4 c1 = *(const float4*)(yp2 + 4);
                d = b0.x - c0.x; s2 = fmaf(d, d, s2);
                d = b0.y - c0.y; s2 = fmaf(d, d, s2);
                d = b0.z - c0.z; s2 = fmaf(d, d, s2);
                d = b0.w - c0.w; s2 = fmaf(d, d, s2);
                d = b1.x - c1.x; s2 = fmaf(d, d, s2);
                d = b1.y - c1.y; s2 = fmaf(d, d, s2);
                d = b1.z - c1.z; s2 = fmaf(d, d, s2);
                d = b1.w - c1.w; s2 = fmaf(d, d, s2);
            }
        }
#pragma unroll
        for (int o = 16; o; o >>= 1) {
            s1 += __shfl_xor_sync(0xffffffffu, s1, o);
            s2 += __shfl_xor_sync(0xffffffffu, s2, o);
        }
        const float vn = sqrtf(s1), vnp = sqrtf(s2);
        const float accv = fabsf(vn - vnp);
        const float risk = sigf(rp[rr] + rb0);
        combined[rr] = 0.5f * risk + 0.3f * sigf(vn) + 0.2f * sigf(accv);
    }
#pragma unroll
    for (int rr = 0; rr < 4; rr++)
        if (lane == rr) bif_out[r0 + rbase + rr] = combined[rr] > 0.7f ? 1.f : 0.f;

    // ---- e8 hidden -> sf (reuse), then e8 code vectors ----
    __syncwarp();
#pragma unroll
    for (int rr = 0; rr < 4; rr++) {
        sf[warp][rr][2 * lane]     = geluf(e1[rr][0]);
        sf[warp][rr][2 * lane + 1] = geluf(e1[rr][1]);
    }
    __syncwarp();

    // lane group: rr = lane>>3, j = lane&7 — all 4 rows' 8 outputs at once
    {
        const int rr = lane >> 3, j = lane & 7;
        float e8c = e8b_b[j];
        for (int k = 0; k < 64; k++)
            e8c = fmaf(sf[warp][rr][k], e8b_w[k * 8 + j], e8c);
        se[warp][rr][j] = e8c;
    }
    __syncwarp();

    // ---- codebook argmin per row ----
#pragma unroll
    for (int rr = 0; rr < 4; rr++) {
        const int r = r0 + rbase + rr;
        const float f0 = se[warp][rr][0], fa = se[warp][rr][1];
        const float fb = se[warp][rr][2], fc = se[warp][rr][3];
        const float fd = se[warp][rr][4], fe = se[warp][rr][5];
        const float ff = se[warp][rr][6], fg = se[warp][rr][7];
        const float fn2 = f0*f0 + fa*fa + fb*fb + fc*fc + fd*fd + fe*fe + ff*ff + fg*fg;

        float best = FLT_MAX;
        int bidx = 0x7fffffff;
        for (int c = lane; c < NCODE; c += 32) {
            const float* cp = cb + c * 8;
            float dot = f0*cp[0] + fa*cp[1] + fb*cp[2] + fc*cp[3]
                      + fd*cp[4] + fe*cp[5] + ff*cp[6] + fg*cp[7];
            float cn2 = cp[0]*cp[0] + cp[1]*cp[1] + cp[2]*cp[2] + cp[3]*cp[3]
                      + cp[4]*cp[4] + cp[5]*cp[5] + cp[6]*cp[6] + cp[7]*cp[7];
            float d2 = fn2 - 2.f * dot + cn2;
            if (d2 < best) { best = d2; bidx = c; }
        }
#pragma unroll
        for (int o = 16; o; o >>= 1) {
            float ob = __shfl_xor_sync(0xffffffffu, best, o);
            int   oi = __shfl_xor_sync(0xffffffffu, bidx, o);
            if (ob < best || (ob == best && oi < bidx)) { best = ob; bidx = oi; }
        }
        if (lane < 8) {
            const float qv = cb[bidx * 8 + lane];
            const float ec = se[warp][rr][lane];
            e8_out[(size_t)r * 8 + lane] = ec + (qv - ec);
        }
        if (lane == 0) idx_out[r] = (float)bidx;
    }
}

// ---------------- launcher ----------------
extern "C" void kernel_launch(void* const* d_in, const int* in_sizes, int n_in,
                              void* d_out, int out_size)
{
    const float* x         = (const float*)d_in[0];
    const float* in_proj_w = (const float*)d_in[1];
    const float* in_proj_b = (const float*)d_in[2];
    const float* conv_w    = (const float*)d_in[3];
    const float* conv_b    = (const float*)d_in[4];
    const float* A_log     = (const float*)d_in[5];
    const float* bc_w      = (const float*)d_in[6];
    const float* bc_b      = (const float*)d_in[7];
    const float* dt_w      = (const float*)d_in[8];
    const float* dt_b      = (const float*)d_in[9];
    const float* out_w     = (const float*)d_in[10];
    const float* out_b     = (const float*)d_in[11];
    const float* cat1_w    = (const float*)d_in[12];
    const float* cat1_b    = (const float*)d_in[13];
    const float* cat2_w    = (const float*)d_in[14];
    const float* cat2_b    = (const float*)d_in[15];
    const float* risk_w    = (const float*)d_in[16];
    const float* risk_b    = (const float*)d_in[17];
    const float* e8a_w     = (const float*)d_in[18];
    const float* e8a_b     = (const float*)d_in[19];
    const float* e8b_w     = (const float*)d_in[20];
    const float* e8b_b     = (const float*)d_in[21];
    const float* cbk       = (const float*)d_in[22];

    float* out = (float*)d_out;
    float* y_out   = out;
    float* e8_out  = out + (size_t)BT * DN;
    float* idx_out = out + (size_t)BT * DN + (size_t)BT * 8;
    float* bif_out = idx_out + BT;

    float *gT, *xc, *xcT, *dtT, *bcT;
    uint32_t *xsh, *xsl, *xmh, *xml, *xch, *xcl, *ygh, *ygl;
    uint32_t *w1h, *w1l, *w2h, *w2l, *w3h, *w3l, *w4h, *w4l;
    cudaGetSymbolAddress((void**)&gT, g_gT);
    cudaGetSymbolAddress((void**)&xc, g_xc);
    cudaGetSymbolAddress((void**)&xcT, g_xcT);
    cudaGetSymbolAddress((void**)&dtT, g_dtT);
    cudaGetSymbolAddress((void**)&bcT, g_bcT);
    cudaGetSymbolAddress((void**)&xsh, g_xsh);
    cudaGetSymbolAddress((void**)&xsl, g_xsl);
    cudaGetSymbolAddress((void**)&xmh, g_xmh);
    cudaGetSymbolAddress((void**)&xml, g_xml);
    cudaGetSymbolAddress((void**)&xch, g_xch);
    cudaGetSymbolAddress((void**)&xcl, g_xcl);
    cudaGetSymbolAddress((void**)&ygh, g_ygh);
    cudaGetSymbolAddress((void**)&ygl, g_ygl);
    cudaGetSymbolAddress((void**)&w1h, g_w1h);
    cudaGetSymbolAddress((void**)&w1l, g_w1l);
    cudaGetSymbolAddress((void**)&w2h, g_w2h);
    cudaGetSymbolAddress((void**)&w2l, g_w2l);
    cudaGetSymbolAddress((void**)&w3h, g_w3h);
    cudaGetSymbolAddress((void**)&w3l, g_w3l);
    cudaGetSymbolAddress((void**)&w4h, g_w4h);
    cudaGetSymbolAddress((void**)&w4l, g_w4l);

    cudaFuncSetAttribute(tgemm<0,3,false,true,false>,  cudaFuncAttributeMaxDynamicSharedMemorySize, SMEMB);
    cudaFuncSetAttribute(tgemm<1,2,false,true,false>,  cudaFuncAttributeMaxDynamicSharedMemorySize, SMEMB);
    cudaFuncSetAttribute(tgemm<2,1,false,false,false>, cudaFuncAttributeMaxDynamicSharedMemorySize, SMEMB);
    cudaFuncSetAttribute(tgemm<0,1,true,false,true>,   cudaFuncAttributeMaxDynamicSharedMemorySize, SMEMB);

    // 0) fused prep (1 launch)
    prep_all<<<(int)((PREP_TOTAL + 255) / 256), 256>>>(
        x, in_proj_w, conv_w, dt_w, out_w,
        xsh, xsl, w1h, w1l, w2h, w2l, w3h, w3l, w4h, w4l);

    // 1) in_proj: bn<512 emit split xmain; bn>=512 gT (silu, transposed)
    tgemm<0,3,false,true,false><<<dim3(8, BT / 128), 256, SMEMB>>>(
        xsh, xsl, 128, w1h, w1l, 128, in_proj_b,
        nullptr, 0, gT, xmh, xml, 256, 256);
    // 2) conv: silu; xc fp32 + xcT + emit split xc
    tgemm<1,2,false,true,false><<<dim3(4, BT / 128), 256, SMEMB>>>(
        xmh, xml, 256, w2h, w2l, 256, conv_b,
        xc, INNER, xcT, xch, xcl, 256, 512);
    // 3) dt: softplus -> dtT (transposed)   [launch #4 for ncu]
    tgemm<2,1,false,false,false><<<dim3(4, BT / 128), 256, SMEMB>>>(
        xch, xcl, 256, w3h, w3l, 256, dt_b,
        nullptr, 0, dtT, nullptr, nullptr, 0, 512);
    // 4) bc -> bcT
    bc_kernel<<<BT / 8, 256>>>(xc, bc_w, bc_b, bcT);
    // 5) scan (+gate) -> split yg [kp][bt]
    scan_kernel<<<dim3(INNER / 16, BN, NCHUNK), 256>>>(xcT, dtT, bcT, A_log, gT, ygh, ygl);
    // 6) out_proj: w4^T (A, ldmatrix) @ yg (B k-major, BKM) -> y_out[bt][j]
    tgemm<0,1,true,false,true><<<dim3(BT / 128, 2), 256, SMEMB>>>(
        w4h, w4l, 256, ygh, ygl, BT, out_b,
        nullptr, 0, y_out, nullptr, nullptr, 0, 512);
    // 7) catastrophe + E8 (4 rows/warp)
    epi_kernel<<<BT / 32, 256>>>(y_out, cat1_w, cat1_b, cat2_w, cat2_b,
                                 risk_w, risk_b, e8a_w, e8a_b, e8b_w, e8b_b,
                                 cbk, e8_out, idx_out, bif_out);
}

// round 15
// speedup vs baseline: 1.2124x; 1.0681x over previous
#include <cuda_runtime.h>
#include <cuda_bf16.h>
#include <math.h>
#include <float.h>
#include <stdint.h>

#define BN 8
#define TN 4096
#define DN 256
#define INNER 512
#define SN 16
#define BT 32768
#define NCODE 240
#define CHUNK 256
#define WARM 32
#define NCHUNK (TN / CHUNK)

// ---------------- scratch ----------------
__device__ float g_gT[(size_t)INNER * BT];
__device__ float g_xc[(size_t)BT * INNER];
__device__ float g_xcT[(size_t)INNER * BT];
__device__ float g_dtT[(size_t)INNER * BT];
__device__ float g_bcT[(size_t)32 * BT];
__device__ uint32_t g_xsh[(size_t)BT * 128], g_xsl[(size_t)BT * 128];
__device__ uint32_t g_xmh[(size_t)BT * 256], g_xml[(size_t)BT * 256];
__device__ uint32_t g_xch[(size_t)BT * 256], g_xcl[(size_t)BT * 256];
__device__ uint32_t g_ygh[(size_t)256 * BT], g_ygl[(size_t)256 * BT];   // [kp][bt]
__device__ uint32_t g_w1h[131072], g_w1l[131072];  // [n=1024][kp=128]
__device__ uint32_t g_w2h[131072], g_w2l[131072];  // [n=512][kp=256]
__device__ uint32_t g_w3h[131072], g_w3l[131072];  // [n=512][kp=256]
__device__ uint32_t g_w4h[65536],  g_w4l[65536];   // out_w^T [m=256][kp=256]

// ---------------- math ----------------
__device__ __forceinline__ float fexp(float x) {
    float t = x * 1.4426950408889634f;
    t = fminf(fmaxf(t, -100.f), 100.f);
    float z = t + 12582912.0f;
    int n = __float_as_int(z) - 0x4B400000;
    float r = t - (z - 12582912.0f);
    float p = 1.5403530394e-4f;
    p = fmaf(p, r, 1.3333558146e-3f);
    p = fmaf(p, r, 9.6181291076e-3f);
    p = fmaf(p, r, 5.5504108664e-2f);
    p = fmaf(p, r, 2.4022650696e-1f);
    p = fmaf(p, r, 6.9314718056e-1f);
    p = fmaf(p, r, 1.0f);
    return __int_as_float(__float_as_int(p) + (n << 23));
}
__device__ __forceinline__ float frcp_fast(float x) {
    float r = __uint_as_float(0x7EF311C3u - __float_as_uint(x));
    r = r * (2.f - x * r); r = r * (2.f - x * r); r = r * (2.f - x * r);
    return r;
}
__device__ __forceinline__ float fsig(float x)  { return frcp_fast(1.f + fexp(-x)); }
__device__ __forceinline__ float fsilu(float x) { return x * fsig(x); }
__device__ __forceinline__ float sigf(float x)  { return 1.f / (1.f + __expf(-x)); }
__device__ __forceinline__ float softplusf(float x) {
    return x > 20.f ? x : __logf(1.f + fexp(x));
}
__device__ __forceinline__ float geluf(float x) {
    const float c = 0.7978845608028654f;
    float t = tanhf(c * (x + 0.044715f * x * x * x));
    return 0.5f * x * (1.f + t);
}
__device__ __forceinline__ void bsplit2(float f0, float f1, uint32_t& hi, uint32_t& lo) {
    __nv_bfloat16 h0 = __float2bfloat16_rn(f0);
    __nv_bfloat16 h1 = __float2bfloat16_rn(f1);
    __nv_bfloat162 hh; hh.x = h0; hh.y = h1;
    hi = *reinterpret_cast<uint32_t*>(&hh);
    __nv_bfloat162 ll = __floats2bfloat162_rn(f0 - __bfloat162float(h0),
                                              f1 - __bfloat162float(h1));
    lo = *reinterpret_cast<uint32_t*>(&ll);
}
__device__ __forceinline__ void mma_bf16(float c[4], const uint32_t a[4], const uint32_t b[2]) {
    asm volatile(
        "mma.sync.aligned.m16n8k16.row.col.f32.bf16.bf16.f32 "
        "{%0,%1,%2,%3}, {%4,%5,%6,%7}, {%8,%9}, {%0,%1,%2,%3};\n"
        : "+f"(c[0]), "+f"(c[1]), "+f"(c[2]), "+f"(c[3])
        : "r"(a[0]), "r"(a[1]), "r"(a[2]), "r"(a[3]), "r"(b[0]), "r"(b[1]));
}
__device__ __forceinline__ void ldsm4(uint32_t& r0, uint32_t& r1, uint32_t& r2,
                                      uint32_t& r3, uint32_t addr) {
    asm volatile("ldmatrix.sync.aligned.m8n8.x4.shared.b16 {%0,%1,%2,%3}, [%4];"
                 : "=r"(r0), "=r"(r1), "=r"(r2), "=r"(r3) : "r"(addr));
}
__device__ __forceinline__ void cp16(uint32_t s, const void* g) {
    asm volatile("cp.async.cg.shared.global [%0], [%1], 16;\n" :: "r"(s), "l"(g));
}
__device__ __forceinline__ void cp_commit() { asm volatile("cp.async.commit_group;\n"); }
__device__ __forceinline__ void cp_wait1()  { asm volatile("cp.async.wait_group 1;\n"); }

// ---------------- fused prep ----------------
__global__ __launch_bounds__(256)
void prep_all(const float* __restrict__ x, const float* __restrict__ w1,
              const float* __restrict__ w2, const float* __restrict__ w3,
              const float* __restrict__ w4,
              uint32_t* __restrict__ xsh, uint32_t* __restrict__ xsl,
              uint32_t* __restrict__ w1h, uint32_t* __restrict__ w1l,
              uint32_t* __restrict__ w2h, uint32_t* __restrict__ w2l,
              uint32_t* __restrict__ w3h, uint32_t* __restrict__ w3l,
              uint32_t* __restrict__ w4h, uint32_t* __restrict__ w4l)
{
    size_t i = (size_t)blockIdx.x * 256 + threadIdx.x;
    const size_t NX = (size_t)BT * 128;
    if (i < NX) {
        float2 v = *(const float2*)(x + 2 * i);
        bsplit2(v.x, v.y, xsh[i], xsl[i]);
        return;
    }
    i -= NX;
    if (i < 131072) {
        int n = (int)(i >> 7), kp = (int)(i & 127);
        bsplit2(w1[(size_t)(2 * kp) * 1024 + n], w1[(size_t)(2 * kp + 1) * 1024 + n],
                w1h[i], w1l[i]);
        return;
    }
    i -= 131072;
    if (i < 131072) {
        int n = (int)(i >> 8), kp = (int)(i & 255);
        bsplit2(w2[(size_t)(2 * kp) * 512 + n], w2[(size_t)(2 * kp + 1) * 512 + n],
                w2h[i], w2l[i]);
        return;
    }
    i -= 131072;
    if (i < 131072) {
        int n = (int)(i >> 8), kp = (int)(i & 255);
        bsplit2(w3[(size_t)(2 * kp) * 512 + n], w3[(size_t)(2 * kp + 1) * 512 + n],
                w3h[i], w3l[i]);
        return;
    }
    i -= 131072;
    if (i < 65536) {
        int m = (int)(i >> 8), kp = (int)(i & 255);
        bsplit2(w4[(size_t)(2 * kp) * 256 + m], w4[(size_t)(2 * kp + 1) * 256 + m],
                w4h[i], w4l[i]);
    }
}
#define PREP_TOTAL ((size_t)BT * 128 + 131072 * 3 + 65536)

// ---------------- bf16x3 GEMM (round-13 proven: cp.async ring + ldmatrix) --
#define PITCH 12
#define BPITCH 136
#define TSTG  (128 * PITCH)
#define SMEMB (12 * TSTG * 4)

template <int EPI, int MODE, bool BROW, bool EMIT, bool BKM>
__global__ __launch_bounds__(256)
void tgemm(const uint32_t* __restrict__ Ah, const uint32_t* __restrict__ Al, int ldaP,
           const uint32_t* __restrict__ Bh, const uint32_t* __restrict__ Bl, int ldbP,
           const float* __restrict__ bias,
           float* __restrict__ C, int ldc, float* __restrict__ Ct,
           uint32_t* __restrict__ Oh, uint32_t* __restrict__ Ol, int ldoP, int K)
{
    extern __shared__ uint32_t smq[];
    const int tid = threadIdx.x, lane = tid & 31, warp = tid >> 5;
    const int wm = warp >> 2, wn = warp & 3;
    const int bm = blockIdx.y * 128, bn = blockIdx.x * 128;
    const int M = gridDim.y * 128;

    const int ar = tid >> 1, ap = (tid & 1) << 2;
    const uint32_t smem0 = (uint32_t)__cvta_generic_to_shared(smq);
    const uint32_t awrd = smem0 + (uint32_t)(ar * PITCH + ap) * 4;
    const uint32_t bwrd_km = smem0 + (uint32_t)(warp * BPITCH + (lane << 2)) * 4;

    const uint32_t* Agh = Ah + (size_t)(bm + ar) * ldaP + ap;
    const uint32_t* Agl = Al + (size_t)(bm + ar) * ldaP + ap;
    const uint32_t* Bgh;
    const uint32_t* Bgl;
    if (BKM) {
        Bgh = Bh + (size_t)warp * ldbP + bn + (lane << 2);
        Bgl = Bl + (size_t)warp * ldbP + bn + (lane << 2);
    } else {
        Bgh = Bh + (size_t)(bn + ar) * ldbP + ap;
        Bgl = Bl + (size_t)(bn + ar) * ldbP + ap;
    }

    const uint32_t aoff = (uint32_t)(((wm * 64 + ((lane >> 3) & 1) * 8 + (lane & 7)) * PITCH
                                      + (lane >> 4) * 4) * 4);
    const uint32_t boff = (uint32_t)(((wn * 32 + ((lane >> 4) & 1) * 8 + (lane & 7)) * PITCH
                                      + ((lane >> 3) & 1) * 4) * 4);

    const int NT = K >> 4;
    float acc[4][4][4];
#pragma unroll
    for (int i = 0; i < 4; i++)
#pragma unroll
        for (int j = 0; j < 4; j++)
#pragma unroll
            for (int r = 0; r < 4; r++) acc[i][j][r] = 0.f;

    auto load_tile = [&](int t, int st) {
        const int kp0 = t * 8;
        cp16(awrd + (uint32_t)((st * 4 + 0) * TSTG) * 4, Agh + kp0);
        cp16(awrd + (uint32_t)((st * 4 + 1) * TSTG) * 4, Agl + kp0);
        if (BKM) {
            cp16(bwrd_km + (uint32_t)((st * 4 + 2) * TSTG) * 4, Bgh + (size_t)kp0 * ldbP);
            cp16(bwrd_km + (uint32_t)((st * 4 + 3) * TSTG) * 4, Bgl + (size_t)kp0 * ldbP);
        } else {
            cp16(awrd + (uint32_t)((st * 4 + 2) * TSTG) * 4, Bgh + kp0);
            cp16(awrd + (uint32_t)((st * 4 + 3) * TSTG) * 4, Bgl + kp0);
        }
    };
    load_tile(0, 0); cp_commit();
    load_tile(1, 1); cp_commit();

    const int tig = lane & 3, gid = lane >> 2;
    int st = 0;
    for (int i = 0; i < NT; i++) {
        cp_wait1();
        __syncthreads();
        int stn = st + 2; if (stn >= 3) stn -= 3;
        if (i + 2 < NT) load_tile(i + 2, stn);
        cp_commit();

        const uint32_t bAh = smem0 + (uint32_t)((st * 4 + 0) * TSTG) * 4;
        const uint32_t bAl = smem0 + (uint32_t)((st * 4 + 1) * TSTG) * 4;

        uint32_t afh[4][4], afl[4][4], bfh[4][2], bfl[4][2];
#pragma unroll
        for (int mf = 0; mf < 4; mf++) {
            ldsm4(afh[mf][0], afh[mf][1], afh[mf][2], afh[mf][3], bAh + aoff + mf * (16 * PITCH * 4));
            ldsm4(afl[mf][0], afl[mf][1], afl[mf][2], afl[mf][3], bAl + aoff + mf * (16 * PITCH * 4));
        }
        if (BKM) {
            const uint32_t* Bsh = smq + (st * 4 + 2) * TSTG;
            const uint32_t* Bsl = smq + (st * 4 + 3) * TSTG;
#pragma unroll
            for (int nf = 0; nf < 4; nf++) {
                const int nn = wn * 32 + nf * 8 + gid;
                bfh[nf][0] = Bsh[tig * BPITCH + nn];
                bfh[nf][1] = Bsh[(tig + 4) * BPITCH + nn];
                bfl[nf][0] = Bsl[tig * BPITCH + nn];
                bfl[nf][1] = Bsl[(tig + 4) * BPITCH + nn];
            }
        } else {
            const uint32_t bBh = smem0 + (uint32_t)((st * 4 + 2) * TSTG) * 4;
            const uint32_t bBl = smem0 + (uint32_t)((st * 4 + 3) * TSTG) * 4;
#pragma unroll
            for (int p = 0; p < 2; p++) {
                ldsm4(bfh[2 * p][0], bfh[2 * p][1], bfh[2 * p + 1][0], bfh[2 * p + 1][1],
                      bBh + boff + p * (16 * PITCH * 4));
                ldsm4(bfl[2 * p][0], bfl[2 * p][1], bfl[2 * p + 1][0], bfl[2 * p + 1][1],
                      bBl + boff + p * (16 * PITCH * 4));
            }
        }
#pragma unroll
        for (int mf = 0; mf < 4; mf++)
#pragma unroll
            for (int nf = 0; nf < 4; nf++)
                mma_bf16(acc[mf][nf], afl[mf], bfh[nf]);
#pragma unroll
        for (int mf = 0; mf < 4; mf++)
#pragma unroll
            for (int nf = 0; nf < 4; nf++)
                mma_bf16(acc[mf][nf], afh[mf], bfl[nf]);
#pragma unroll
        for (int mf = 0; mf < 4; mf++)
#pragma unroll
            for (int nf = 0; nf < 4; nf++)
                mma_bf16(acc[mf][nf], afh[mf], bfh[nf]);

        st = (st + 1 == 3) ? 0 : st + 1;
    }

#pragma unroll
    for (int mf = 0; mf < 4; mf++) {
#pragma unroll
        for (int nf = 0; nf < 4; nf++) {
            const int col = wn * 32 + nf * 8 + tig * 2;
            const int row = wm * 64 + mf * 16 + gid;
            float b0, b1, b2, b3;
            if (BROW) { b0 = b1 = bias[bm + row]; b2 = b3 = bias[bm + row + 8]; }
            else      { b0 = b2 = bias[bn + col]; b1 = b3 = bias[bn + col + 1]; }
            float v0 = acc[mf][nf][0] + b0;
            float v1 = acc[mf][nf][1] + b1;
            float v2 = acc[mf][nf][2] + b2;
            float v3 = acc[mf][nf][3] + b3;
            if (MODE != 3) {
                if (EPI == 1) { v0 = fsilu(v0); v1 = fsilu(v1); v2 = fsilu(v2); v3 = fsilu(v3); }
                else if (EPI == 2) { v0 = softplusf(v0); v1 = softplusf(v1); v2 = softplusf(v2); v3 = softplusf(v3); }
            }
            if (MODE == 0 || MODE == 2) {
                float* p0 = C + (size_t)(bm + row) * ldc + bn + col;
                float* p1 = C + (size_t)(bm + row + 8) * ldc + bn + col;
                *(float2*)p0 = make_float2(v0, v1);
                *(float2*)p1 = make_float2(v2, v3);
            }
            if (EMIT && (MODE != 3 || bn < 512)) {
                uint32_t h0, l0, h1, l1;
                bsplit2(v0, v1, h0, l0);
                bsplit2(v2, v3, h1, l1);
                const size_t o0 = (size_t)(bm + row) * ldoP + ((bn + col) >> 1);
                const size_t o1 = (size_t)(bm + row + 8) * ldoP + ((bn + col) >> 1);
                Oh[o0] = h0; Ol[o0] = l0;
                Oh[o1] = h1; Ol[o1] = l1;
            }
            if (MODE == 1 || MODE == 2 || (MODE == 3 && bn >= 512)) {
                float w0 = v0, w1 = v1, w2 = v2, w3 = v3;
                if (MODE == 3) { w0 = fsilu(w0); w1 = fsilu(w1); w2 = fsilu(w2); w3 = fsilu(w3); }
                const int coff = (MODE == 3) ? (bn - 512) : bn;
                float* q0 = Ct + (size_t)(coff + col) * M + bm + row;
                float* q1 = Ct + (size_t)(coff + col + 1) * M + bm + row;
                q0[0] = w0; q1[0] = w1; q0[8] = w2; q1[8] = w3;
            }
        }
    }
}

// ---------------- bc projection -> bcT [32][BT] ----------------
__global__ __launch_bounds__(256)
void bc_kernel(const float* __restrict__ xc, const float* __restrict__ w,
               const float* __restrict__ bias, float* __restrict__ bcT)
{
    __shared__ float srow[8][512];
    __shared__ float sbc[8][33];
    const int warp = threadIdx.x >> 5, lane = threadIdx.x & 31;
    const int r0 = blockIdx.x * 8, r = r0 + warp;
    const float* xr = xc + (size_t)r * INNER;
    for (int k = lane; k < INNER; k += 32) srow[warp][k] = xr[k];
    __syncwarp();
    float acc = bias[lane];
#pragma unroll 4
    for (int k = 0; k < INNER; k++)
        acc = fmaf(srow[warp][k], w[k * 32 + lane], acc);
    sbc[warp][lane] = acc;
    __syncthreads();
    const int j = threadIdx.x >> 3, rr = threadIdx.x & 7;
    bcT[(size_t)j * BT + r0 + rr] = sbc[rr][j];
}

// ---------------- chunked scan v2: 8 s-lanes x 4 d, 2 states/thread --------
// warp: q = lane>>3 selects d (4 per warp), sl = lane&7 owns states 2sl, 2sl+1.
// emits split yg [kp][bt] (lanes 0 and 16 store each warp's two kp streams).
__global__ __launch_bounds__(256)
void scan_kernel(const float* __restrict__ xcT, const float* __restrict__ dtT,
                 const float* __restrict__ bcT, const float* __restrict__ A_log,
                 const float* __restrict__ gT,
                 uint32_t* __restrict__ ygh, uint32_t* __restrict__ ygl)
{
    __shared__ float sbc[32][292];
    const int lane = threadIdx.x & 31, warp = threadIdx.x >> 5;
    const int sl = lane & 7, q = lane >> 3;
    const int s0 = 2 * sl, s1 = s0 + 1;
    const int b = blockIdx.y, c = blockIdx.z;
    const int d = blockIdx.x * 32 + warp * 4 + q;
    const int kp0 = blockIdx.x * 16 + warp * 2;

    const int tout = c * CHUNK;
    const int off0 = (c > 0) ? tout - WARM : tout;
    const int len  = (c > 0) ? CHUNK + WARM : CHUNK;
    {
        const float* src = bcT + (size_t)b * TN + off0;
        const int q4 = len >> 2;
        for (int i = threadIdx.x; i < 32 * q4; i += 256) {
            const int r = i / q4, j = i - r * q4;
            *(float4*)&sbc[r][4 * j] = *(const float4*)(src + (size_t)r * BT + 4 * j);
        }
    }
    const float As0 = -__expf(A_log[d * SN + s0]);
    const float As1 = -__expf(A_log[d * SN + s1]);
    const size_t dbase = (size_t)d * BT + (size_t)b * TN;
    __syncthreads();

    float h0 = 0.f, h1 = 0.f;
    if (c > 0) {
        const int tw = tout - WARM;
        const float4* dtw = (const float4*)(dtT + dbase + tw);
        const float4* xcw = (const float4*)(xcT + dbase + tw);
#pragma unroll
        for (int i = 0; i < WARM / 4; i++) {
            const float4 dt4 = dtw[i], xc4 = xcw[i];
            const float4 B0 = *(const float4*)&sbc[s0][4 * i];
            const float4 B1 = *(const float4*)&sbc[s1][4 * i];
            float dtx;
            dtx = dt4.x * xc4.x;
            h0 = fmaf(__expf(dt4.x * As0), h0, dtx * B0.x);
            h1 = fmaf(__expf(dt4.x * As1), h1, dtx * B1.x);
            dtx = dt4.y * xc4.y;
            h0 = fmaf(__expf(dt4.y * As0), h0, dtx * B0.y);
            h1 = fmaf(__expf(dt4.y * As1), h1, dtx * B1.y);
            dtx = dt4.z * xc4.z;
            h0 = fmaf(__expf(dt4.z * As0), h0, dtx * B0.z);
            h1 = fmaf(__expf(dt4.z * As1), h1, dtx * B1.z);
            dtx = dt4.w * xc4.w;
            h0 = fmaf(__expf(dt4.w * As0), h0, dtx * B0.w);
            h1 = fmaf(__expf(dt4.w * As1), h1, dtx * B1.w);
        }
    }
    const int base = (c > 0) ? WARM : 0;
    const float4* dt4p = (const float4*)(dtT + dbase + tout);
    const float4* xc4p = (const float4*)(xcT + dbase + tout);
    const float4* g4p  = (const float4*)(gT  + dbase + tout);

    for (int i = 0; i < CHUNK / 4; i++) {
        const float4 dt4 = dt4p[i], xc4 = xc4p[i];
        const float4 B0 = *(const float4*)&sbc[s0][base + 4 * i];
        const float4 B1 = *(const float4*)&sbc[s1][base + 4 * i];
        const float4 C0 = *(const float4*)&sbc[16 + s0][base + 4 * i];
        const float4 C1 = *(const float4*)&sbc[16 + s1][base + 4 * i];
        float dtx;
        dtx = dt4.x * xc4.x;
        h0 = fmaf(__expf(dt4.x * As0), h0, dtx * B0.x);
        h1 = fmaf(__expf(dt4.x * As1), h1, dtx * B1.x);
        float y0 = fmaf(h1, C1.x, h0 * C0.x);
        dtx = dt4.y * xc4.y;
        h0 = fmaf(__expf(dt4.y * As0), h0, dtx * B0.y);
        h1 = fmaf(__expf(dt4.y * As1), h1, dtx * B1.y);
        float y1 = fmaf(h1, C1.y, h0 * C0.y);
        dtx = dt4.z * xc4.z;
        h0 = fmaf(__expf(dt4.z * As0), h0, dtx * B0.z);
        h1 = fmaf(__expf(dt4.z * As1), h1, dtx * B1.z);
        float y2 = fmaf(h1, C1.z, h0 * C0.z);
        dtx = dt4.w * xc4.w;
        h0 = fmaf(__expf(dt4.w * As0), h0, dtx * B0.w);
        h1 = fmaf(__expf(dt4.w * As1), h1, dtx * B1.w);
        float y3 = fmaf(h1, C1.w, h0 * C0.w);

#pragma unroll
        for (int o = 1; o <= 4; o <<= 1) {
            y0 += __shfl_xor_sync(0xffffffffu, y0, o);
            y1 += __shfl_xor_sync(0xffffffffu, y1, o);
            y2 += __shfl_xor_sync(0xffffffffu, y2, o);
            y3 += __shfl_xor_sync(0xffffffffu, y3, o);
        }
        const float4 g4 = g4p[i];
        const float z0 = y0 * g4.x, z1 = y1 * g4.y, z2 = y2 * g4.z, z3 = y3 * g4.w;
        const float p0 = __shfl_xor_sync(0xffffffffu, z0, 8);
        const float p1 = __shfl_xor_sync(0xffffffffu, z1, 8);
        const float p2 = __shfl_xor_sync(0xffffffffu, z2, 8);
        const float p3 = __shfl_xor_sync(0xffffffffu, z3, 8);
        if ((lane & 15) == 0) {
            uint4 hv, lv;
            bsplit2(z0, p0, hv.x, lv.x);
            bsplit2(z1, p1, hv.y, lv.y);
            bsplit2(z2, p2, hv.z, lv.z);
            bsplit2(z3, p3, hv.w, lv.w);
            const size_t o = (size_t)(kp0 + (lane >> 4)) * BT + (size_t)b * TN + tout + 4 * i;
            *(uint4*)(ygh + o) = hv;
            *(uint4*)(ygl + o) = lv;
        }
    }
}

// ---------------- catastrophe + E8 (round-13, 4 rows/warp) -----------------
__global__ __launch_bounds__(256)
void epi_kernel(const float* __restrict__ y,
                const float* __restrict__ cat1_w, const float* __restrict__ cat1_b,
                const float* __restrict__ cat2_w, const float* __restrict__ cat2_b,
                const float* __restrict__ risk_w, const float* __restrict__ risk_b,
                const float* __restrict__ e8a_w,  const float* __restrict__ e8a_b,
                const float* __restrict__ e8b_w,  const float* __restrict__ e8b_b,
                const float* __restrict__ cb,
                float* __restrict__ e8_out, float* __restrict__ idx_out,
                float* __restrict__ bif_out)
{
    __shared__ float sy[32][264];
    __shared__ float sf[8][4][64];
    __shared__ float se[8][4][8];

    const int tid = threadIdx.x, warp = tid >> 5, lane = tid & 31;
    const int r0 = blockIdx.x * 32;
    const int rbase = warp * 4;

    for (int i = tid; i < 32 * 64; i += 256) {
        const int row = i >> 6, j = i & 63;
        *(float4*)&sy[row][4 * j] = *(const float4*)(y + (size_t)(r0 + row) * DN + 4 * j);
    }
    __syncthreads();

    float f1[4][2], e1[4][2];
    {
        const float2 cb2 = *(const float2*)(cat1_b + 2 * lane);
        const float2 eb2 = *(const float2*)(e8a_b + 2 * lane);
#pragma unroll
        for (int rr = 0; rr < 4; rr++) {
            f1[rr][0] = cb2.x; f1[rr][1] = cb2.y;
            e1[rr][0] = eb2.x; e1[rr][1] = eb2.y;
        }
    }
    for (int k = 0; k < DN; k++) {
        const float2 wc = *(const float2*)(cat1_w + k * 64 + 2 * lane);
        const float2 we = *(const float2*)(e8a_w + k * 64 + 2 * lane);
#pragma unroll
        for (int rr = 0; rr < 4; rr++) {
            const float yv = sy[rbase + rr][k];
            f1[rr][0] = fmaf(yv, wc.x, f1[rr][0]);
            f1[rr][1] = fmaf(yv, wc.y, f1[rr][1]);
            e1[rr][0] = fmaf(yv, we.x, e1[rr][0]);
            e1[rr][1] = fmaf(yv, we.y, e1[rr][1]);
        }
    }
#pragma unroll
    for (int rr = 0; rr < 4; rr++) {
        sf[warp][rr][2 * lane]     = geluf(f1[rr][0]);
        sf[warp][rr][2 * lane + 1] = geluf(f1[rr][1]);
    }
    __syncwarp();

    float f2[4];
    {
        const float c2b = cat2_b[lane];
#pragma unroll
        for (int rr = 0; rr < 4; rr++) f2[rr] = c2b;
    }
    for (int k = 0; k < 64; k++) {
        const float w = cat2_w[k * 32 + lane];
#pragma unroll
        for (int rr = 0; rr < 4; rr++)
            f2[rr] = fmaf(sf[warp][rr][k], w, f2[rr]);
    }
    float rp[4];
    {
        const float rw = risk_w[lane];
#pragma unroll
        for (int rr = 0; rr < 4; rr++) rp[rr] = f2[rr] * rw;
    }
#pragma unroll
    for (int o = 16; o; o >>= 1)
#pragma unroll
        for (int rr = 0; rr < 4; rr++)
            rp[rr] += __shfl_xor_sync(0xffffffffu, rp[rr], o);
    const float rb0 = risk_b[0];

    float combined[4];
#pragma unroll
    for (int rr = 0; rr < 4; rr++) {
        const int r = r0 + rbase + rr;
        const int t = r & (TN - 1);
        float s1 = 0.f, s2 = 0.f;
        if (t > 0) {
            const int k0 = lane * 8;
            const float* yp1 = y + (size_t)(r - 1) * DN + k0;
            const float4 a0 = *(const float4*)&sy[rbase + rr][k0];
            const float4 a1 = *(const float4*)&sy[rbase + rr][k0 + 4];
            const float4 b0 = *(const float4*)(yp1);
            const float4 b1 = *(const float4*)(yp1 + 4);
            float d;
            d = a0.x - b0.x; s1 = fmaf(d, d, s1);
            d = a0.y - b0.y; s1 = fmaf(d, d, s1);
            d = a0.z - b0.z; s1 = fmaf(d, d, s1);
            d = a0.w - b0.w; s1 = fmaf(d, d, s1);
            d = a1.x - b1.x; s1 = fmaf(d, d, s1);
            d = a1.y - b1.y; s1 = fmaf(d, d, s1);
            d = a1.z - b1.z; s1 = fmaf(d, d, s1);
            d = a1.w - b1.w; s1 = fmaf(d, d, s1);
            if (t > 1) {
                const float* yp2 = y + (size_t)(r - 2) * DN + k0;
                const float4 c0 = *(const float4*)(yp2);
                const float4 c1 = *(const float4*)(yp2 + 4);
                d = b0.x - c0.x; s2 = fmaf(d, d, s2);
                d = b0.y - c0.y; s2 = fmaf(d, d, s2);
                d = b0.z - c0.z; s2 = fmaf(d, d, s2);
                d = b0.w - c0.w; s2 = fmaf(d, d, s2);
                d = b1.x - c1.x; s2 = fmaf(d, d, s2);
                d = b1.y - c1.y; s2 = fmaf(d, d, s2);
                d = b1.z - c1.z; s2 = fmaf(d, d, s2);
                d = b1.w - c1.w; s2 = fmaf(d, d, s2);
            }
        }
#pragma unroll
        for (int o = 16; o; o >>= 1) {
            s1 += __shfl_xor_sync(0xffffffffu, s1, o);
            s2 += __shfl_xor_sync(0xffffffffu, s2, o);
        }
        const float vn = sqrtf(s1), vnp = sqrtf(s2);
        const float accv = fabsf(vn - vnp);
        const float risk = sigf(rp[rr] + rb0);
        combined[rr] = 0.5f * risk + 0.3f * sigf(vn) + 0.2f * sigf(accv);
    }
#pragma unroll
    for (int rr = 0; rr < 4; rr++)
        if (lane == rr) bif_out[r0 + rbase + rr] = combined[rr] > 0.7f ? 1.f : 0.f;

    __syncwarp();
#pragma unroll
    for (int rr = 0; rr < 4; rr++) {
        sf[warp][rr][2 * lane]     = geluf(e1[rr][0]);
        sf[warp][rr][2 * lane + 1] = geluf(e1[rr][1]);
    }
    __syncwarp();
    {
        const int rr = lane >> 3, j = lane & 7;
        float e8c = e8b_b[j];
        for (int k = 0; k < 64; k++)
            e8c = fmaf(sf[warp][rr][k], e8b_w[k * 8 + j], e8c);
        se[warp][rr][j] = e8c;
    }
    __syncwarp();

#pragma unroll
    for (int rr = 0; rr < 4; rr++) {
        const int r = r0 + rbase + rr;
        const float f0 = se[warp][rr][0], fa = se[warp][rr][1];
        const float fb = se[warp][rr][2], fc = se[warp][rr][3];
        const float fd = se[warp][rr][4], fe = se[warp][rr][5];
        const float ff = se[warp][rr][6], fg = se[warp][rr][7];
        const float fn2 = f0*f0 + fa*fa + fb*fb + fc*fc + fd*fd + fe*fe + ff*ff + fg*fg;

        float best = FLT_MAX;
        int bidx = 0x7fffffff;
        for (int c = lane; c < NCODE; c += 32) {
            const float* cp = cb + c * 8;
            float dot = f0*cp[0] + fa*cp[1] + fb*cp[2] + fc*cp[3]
                      + fd*cp[4] + fe*cp[5] + ff*cp[6] + fg*cp[7];
            float cn2 = cp[0]*cp[0] + cp[1]*cp[1] + cp[2]*cp[2] + cp[3]*cp[3]
                      + cp[4]*cp[4] + cp[5]*cp[5] + cp[6]*cp[6] + cp[7]*cp[7];
            float d2 = fn2 - 2.f * dot + cn2;
            if (d2 < best) { best = d2; bidx = c; }
        }
#pragma unroll
        for (int o = 16; o; o >>= 1) {
            float ob = __shfl_xor_sync(0xffffffffu, best, o);
            int   oi = __shfl_xor_sync(0xffffffffu, bidx, o);
            if (ob < best || (ob == best && oi < bidx)) { best = ob; bidx = oi; }
        }
        if (lane < 8) {
            const float qv = cb[bidx * 8 + lane];
            const float ec = se[warp][rr][lane];
            e8_out[(size_t)r * 8 + lane] = ec + (qv - ec);
        }
        if (lane == 0) idx_out[r] = (float)bidx;
    }
}

// ---------------- launcher ----------------
extern "C" void kernel_launch(void* const* d_in, const int* in_sizes, int n_in,
                              void* d_out, int out_size)
{
    const float* x         = (const float*)d_in[0];
    const float* in_proj_w = (const float*)d_in[1];
    const float* in_proj_b = (const float*)d_in[2];
    const float* conv_w    = (const float*)d_in[3];
    const float* conv_b    = (const float*)d_in[4];
    const float* A_log     = (const float*)d_in[5];
    const float* bc_w      = (const float*)d_in[6];
    const float* bc_b      = (const float*)d_in[7];
    const float* dt_w      = (const float*)d_in[8];
    const float* dt_b      = (const float*)d_in[9];
    const float* out_w     = (const float*)d_in[10];
    const float* out_b     = (const float*)d_in[11];
    const float* cat1_w    = (const float*)d_in[12];
    const float* cat1_b    = (const float*)d_in[13];
    const float* cat2_w    = (const float*)d_in[14];
    const float* cat2_b    = (const float*)d_in[15];
    const float* risk_w    = (const float*)d_in[16];
    const float* risk_b    = (const float*)d_in[17];
    const float* e8a_w     = (const float*)d_in[18];
    const float* e8a_b     = (const float*)d_in[19];
    const float* e8b_w     = (const float*)d_in[20];
    const float* e8b_b     = (const float*)d_in[21];
    const float* cbk       = (const float*)d_in[22];

    float* out = (float*)d_out;
    float* y_out   = out;
    float* e8_out  = out + (size_t)BT * DN;
    float* idx_out = out + (size_t)BT * DN + (size_t)BT * 8;
    float* bif_out = idx_out + BT;

    float *gT, *xc, *xcT, *dtT, *bcT;
    uint32_t *xsh, *xsl, *xmh, *xml, *xch, *xcl, *ygh, *ygl;
    uint32_t *w1h, *w1l, *w2h, *w2l, *w3h, *w3l, *w4h, *w4l;
    cudaGetSymbolAddress((void**)&gT, g_gT);
    cudaGetSymbolAddress((void**)&xc, g_xc);
    cudaGetSymbolAddress((void**)&xcT, g_xcT);
    cudaGetSymbolAddress((void**)&dtT, g_dtT);
    cudaGetSymbolAddress((void**)&bcT, g_bcT);
    cudaGetSymbolAddress((void**)&xsh, g_xsh);
    cudaGetSymbolAddress((void**)&xsl, g_xsl);
    cudaGetSymbolAddress((void**)&xmh, g_xmh);
    cudaGetSymbolAddress((void**)&xml, g_xml);
    cudaGetSymbolAddress((void**)&xch, g_xch);
    cudaGetSymbolAddress((void**)&xcl, g_xcl);
    cudaGetSymbolAddress((void**)&ygh, g_ygh);
    cudaGetSymbolAddress((void**)&ygl, g_ygl);
    cudaGetSymbolAddress((void**)&w1h, g_w1h);
    cudaGetSymbolAddress((void**)&w1l, g_w1l);
    cudaGetSymbolAddress((void**)&w2h, g_w2h);
    cudaGetSymbolAddress((void**)&w2l, g_w2l);
    cudaGetSymbolAddress((void**)&w3h, g_w3h);
    cudaGetSymbolAddress((void**)&w3l, g_w3l);
    cudaGetSymbolAddress((void**)&w4h, g_w4h);
    cudaGetSymbolAddress((void**)&w4l, g_w4l);

    cudaFuncSetAttribute(tgemm<0,3,false,true,false>,  cudaFuncAttributeMaxDynamicSharedMemorySize, SMEMB);
    cudaFuncSetAttribute(tgemm<1,2,false,true,false>,  cudaFuncAttributeMaxDynamicSharedMemorySize, SMEMB);
    cudaFuncSetAttribute(tgemm<2,1,false,false,false>, cudaFuncAttributeMaxDynamicSharedMemorySize, SMEMB);
    cudaFuncSetAttribute(tgemm<0,1,true,false,true>,   cudaFuncAttributeMaxDynamicSharedMemorySize, SMEMB);

    // 0) fused prep
    prep_all<<<(int)((PREP_TOTAL + 255) / 256), 256>>>(
        x, in_proj_w, conv_w, dt_w, out_w,
        xsh, xsl, w1h, w1l, w2h, w2l, w3h, w3l, w4h, w4l);

    // 1) in_proj: bn<512 emit split xmain; bn>=512 gT (silu, transposed)
    tgemm<0,3,false,true,false><<<dim3(8, BT / 128), 256, SMEMB>>>(
        xsh, xsl, 128, w1h, w1l, 128, in_proj_b,
        nullptr, 0, gT, xmh, xml, 256, 256);
    // 2) conv: silu; xc fp32 + xcT + emit split xc
    tgemm<1,2,false,true,false><<<dim3(4, BT / 128), 256, SMEMB>>>(
        xmh, xml, 256, w2h, w2l, 256, conv_b,
        xc, INNER, xcT, xch, xcl, 256, 512);
    // 3) dt: softplus -> dtT (transposed)
    tgemm<2,1,false,false,false><<<dim3(4, BT / 128), 256, SMEMB>>>(
        xch, xcl, 256, w3h, w3l, 256, dt_b,
        nullptr, 0, dtT, nullptr, nullptr, 0, 512);
    // 4) bc -> bcT
    bc_kernel<<<BT / 8, 256>>>(xc, bc_w, bc_b, bcT);
    // 5) scan v2 (+gate) -> split yg [kp][bt]
    scan_kernel<<<dim3(INNER / 32, BN, NCHUNK), 256>>>(xcT, dtT, bcT, A_log, gT, ygh, ygl);
    // 6) out_proj: w4^T (A, ldmatrix) @ yg (B k-major, BKM) -> y_out[bt][j]
    tgemm<0,1,true,false,true><<<dim3(BT / 128, 2), 256, SMEMB>>>(
        w4h, w4l, 256, ygh, ygl, BT, out_b,
        nullptr, 0, y_out, nullptr, nullptr, 0, 512);
    // 7) catastrophe + E8 (4 rows/warp)
    epi_kernel<<<BT / 32, 256>>>(y_out, cat1_w, cat1_b, cat2_w, cat2_b,
                                 risk_w, risk_b, e8a_w, e8a_b, e8b_w, e8b_b,
                                 cbk, e8_out, idx_out, bif_out);
}